// round 13
// baseline (speedup 1.0000x reference)
#include <cuda_runtime.h>
#include <cuda_fp16.h>
#include <math.h>
#include <stdint.h>

// Problem constants
#define Bx 2
#define Tx 16
#define Lx 256
#define Dx 1152
#define NHx 16
#define HDx 72
#define MLPH 3072
#define NTOK 8192          // B*T*L
#define D3 3456
#define D9 10368

// ---------------- scratch (device globals) --------------------------------
__device__ float g_sc[Bx * Dx];
__device__ float g_ch[Bx * D9];
__device__ __half g_xn[(size_t)NTOK * Dx];
__device__ __half g_bigh[(size_t)NTOK * 2 * MLPH];
__device__ __half g_h[(size_t)NTOK * MLPH];
// transposed (half) weights, [N, K] K-major
__device__ __half g_wt_qkv_s[(size_t)D3 * Dx];
__device__ __half g_wt_qkv_t[(size_t)D3 * Dx];
__device__ __half g_wt_proj_s[(size_t)Dx * Dx];
__device__ __half g_wt_proj_t[(size_t)Dx * Dx];
__device__ __half g_wt_w12[(size_t)2 * MLPH * Dx];
__device__ __half g_wt_w3[(size_t)Dx * MLPH];

// ---------------- side stream + events (load-time init) --------------------
struct SideStream {
    cudaStream_t s;
    cudaEvent_t evRoot, evA, evB;
    SideStream() {
        cudaStreamCreateWithFlags(&s, cudaStreamNonBlocking);
        cudaEventCreateWithFlags(&evRoot, cudaEventDisableTiming);
        cudaEventCreateWithFlags(&evA, cudaEventDisableTiming);
        cudaEventCreateWithFlags(&evB, cudaEventDisableTiming);
    }
};
static SideStream g_ss;

// ---------------- helpers ---------------------------------------------------
__device__ __forceinline__ uint32_t smem_u32(const void* p) {
    return (uint32_t)__cvta_generic_to_shared(p);
}

#define CP_ASYNC16(dst, src) \
    asm volatile("cp.async.cg.shared.global [%0], [%1], 16;" :: "r"(dst), "l"(src) : "memory")
#define CP_COMMIT() asm volatile("cp.async.commit_group;" ::: "memory")
#define CP_WAIT1()  asm volatile("cp.async.wait_group 1;" ::: "memory")
#define CP_WAIT0()  asm volatile("cp.async.wait_group 0;" ::: "memory")

#define MMA_F16(d, a, b) \
    asm volatile( \
        "mma.sync.aligned.m16n8k16.row.col.f32.f16.f16.f32 " \
        "{%0,%1,%2,%3}, {%4,%5,%6,%7}, {%8,%9}, {%0,%1,%2,%3};" \
        : "+f"((d)[0]), "+f"((d)[1]), "+f"((d)[2]), "+f"((d)[3]) \
        : "r"((a)[0]), "r"((a)[1]), "r"((a)[2]), "r"((a)[3]), \
          "r"((b)[0]), "r"((b)[1]))

#define LDMX4(r0, r1, r2, r3, addr) \
    asm volatile("ldmatrix.sync.aligned.m8n8.x4.shared.b16 {%0,%1,%2,%3}, [%4];" \
                 : "=r"(r0), "=r"(r1), "=r"(r2), "=r"(r3) : "r"(addr))
#define LDMX2(r0, r1, addr) \
    asm volatile("ldmatrix.sync.aligned.m8n8.x2.shared.b16 {%0,%1}, [%2];" \
                 : "=r"(r0), "=r"(r1) : "r"(addr))

__device__ __forceinline__ void st2(float* p, float a, float b) {
    *reinterpret_cast<float2*>(p) = make_float2(a, b);
}
__device__ __forceinline__ void st2(__half* p, float a, float b) {
    *reinterpret_cast<__half2*>(p) = __floats2half2_rn(a, b);
}
__device__ __forceinline__ uint32_t packh2(float a, float b) {
    __half2 h = __floats2half2_rn(a, b);
    return *reinterpret_cast<uint32_t*>(&h);
}
__device__ __forceinline__ float fexp2(float y) {
    float t = y + 12582912.f;
    int n = __float_as_int(t) - __float_as_int(12582912.f);
    float f = y - (t - 12582912.f);
    float p = 0.0013333558f;
    p = fmaf(p, f, 0.0096181291f);
    p = fmaf(p, f, 0.0555041087f);
    p = fmaf(p, f, 0.2402265070f);
    p = fmaf(p, f, 0.6931471806f);
    p = fmaf(p, f, 1.0f);
    return __int_as_float(__float_as_int(p) + (n << 23));
}

// ---------------- weight transposes to half --------------------------------
__global__ void transpose_h_kernel(const float* __restrict__ W, __half* __restrict__ Wt,
                                   int K, int N) {
    __shared__ float t[32][33];
    int n0 = blockIdx.x * 32, k0 = blockIdx.y * 32;
#pragma unroll
    for (int r = 0; r < 4; r++)
        t[threadIdx.y + r * 8][threadIdx.x] =
            W[(size_t)(k0 + threadIdx.y + r * 8) * N + n0 + threadIdx.x];
    __syncthreads();
#pragma unroll
    for (int r = 0; r < 4; r++)
        Wt[(size_t)(n0 + threadIdx.y + r * 8) * K + k0 + threadIdx.x] =
            __float2half_rn(t[threadIdx.x][threadIdx.y + r * 8]);
}

__global__ void transpose_h_il_kernel(const float* __restrict__ W, __half* __restrict__ Wt,
                                      int K, int N) {
    __shared__ float t[32][33];
    int n0 = blockIdx.x * 32, k0 = blockIdx.y * 32;
    int nn = n0 + threadIdx.x;
    int src = (nn >> 1) + (nn & 1) * MLPH;
#pragma unroll
    for (int r = 0; r < 4; r++)
        t[threadIdx.y + r * 8][threadIdx.x] =
            W[(size_t)(k0 + threadIdx.y + r * 8) * N + src];
    __syncthreads();
#pragma unroll
    for (int r = 0; r < 4; r++)
        Wt[(size_t)(n0 + threadIdx.y + r * 8) * K + k0 + threadIdx.x] =
            __float2half_rn(t[threadIdx.x][threadIdx.y + r * 8]);
}

// ---------------- fp16 mma.sync GEMM v5: persistent tiles ------------------
// 128x128x64 tile, 8 warps x (64x32), 3-stage cp.async pipeline carried
// ACROSS tile boundaries (cross-tile prefetch), single sync per k-step,
// 2 CTAs/SM. K % 64 == 0. grid.x = min(ntiles, 296).
#define BM3 128
#define BN3 128
#define LDH 72
#define STG3 (256 * LDH)
#define GM3_SMEM (3 * STG3 * 2)

template <int EPI, typename OutT>
__global__ __launch_bounds__(256, 2) void gemm3_kernel(
    const __half* __restrict__ A, const __half* __restrict__ Bt,
    const float* __restrict__ bias, OutT* __restrict__ C,
    int M, int N, int K,
    const float* __restrict__ base, const float* __restrict__ ch,
    int gate_slot, int mode) {
    extern __shared__ __half sh[];
    int tid = threadIdx.x;
    int wid = tid >> 5, lane = tid & 31;
    int g = lane >> 2, tig = lane & 3;
    int wm = (wid & 1) * 64, wn = (wid >> 1) * 32;
    int loff = ((lane & 7) + ((lane >> 3) & 1) * 8) * LDH + (lane >> 4) * 8;
    int row8 = tid >> 3, c8 = tid & 7;

    const int nx = N / BN3;
    const int ntiles = nx * (M / BM3);
    const int kt = K >> 6;
    const int G = gridDim.x;

    int tile = blockIdx.x;
    int pf_tile = tile, pf_t = 0;
    int stage = 0;

    // issue one k-stage of loads for (pf_tile, pf_t) into pstage
#define ISSUE_PF(pstage)                                                          \
    do {                                                                          \
        int bx_ = pf_tile % nx, by_ = pf_tile / nx;                              \
        const __half* Ab_ = A + (size_t)(by_ * BM3) * K;                         \
        const __half* Bb_ = Bt + (size_t)(bx_ * BN3) * K;                        \
        __half* dA_ = sh + (pstage) * STG3;                                       \
        __half* dB_ = dA_ + 128 * LDH;                                            \
        int k0_ = pf_t * 64;                                                      \
        _Pragma("unroll") for (int r_ = 0; r_ < 4; r_++) {                        \
            int row_ = row8 + r_ * 32;                                            \
            CP_ASYNC16(smem_u32(dA_ + row_ * LDH + c8 * 8),                       \
                       Ab_ + (size_t)row_ * K + k0_ + c8 * 8);                    \
            CP_ASYNC16(smem_u32(dB_ + row_ * LDH + c8 * 8),                       \
                       Bb_ + (size_t)row_ * K + k0_ + c8 * 8);                    \
        }                                                                         \
        CP_COMMIT();                                                              \
        pf_t++;                                                                   \
        if (pf_t == kt) { pf_t = 0; pf_tile += G; }                               \
    } while (0)

    // prologue: 2 stages
    ISSUE_PF(0);
    ISSUE_PF(1);

    while (tile < ntiles) {
        float acc[4][4][4];
#pragma unroll
        for (int mi = 0; mi < 4; mi++)
#pragma unroll
            for (int ni = 0; ni < 4; ni++)
#pragma unroll
                for (int r = 0; r < 4; r++) acc[mi][ni][r] = 0.f;

        for (int t = 0; t < kt; t++) {
            bool havepf = (pf_tile < ntiles);
            if (havepf) { CP_WAIT1(); } else { CP_WAIT0(); }
            __syncthreads();
            if (havepf) ISSUE_PF((stage + 2) % 3);

            const __half* tA = sh + stage * STG3;
            const __half* tB = tA + 128 * LDH;
#pragma unroll
            for (int kk = 0; kk < 4; kk++) {
                int cb = kk * 16;
                uint32_t afr[4][4];
                uint32_t bfr[4][2];
#pragma unroll
                for (int mi = 0; mi < 4; mi++) {
                    uint32_t ad = smem_u32(tA + (wm + 16 * mi) * LDH + cb + loff);
                    LDMX4(afr[mi][0], afr[mi][1], afr[mi][2], afr[mi][3], ad);
                }
#pragma unroll
                for (int nj = 0; nj < 2; nj++) {
                    uint32_t bd = smem_u32(tB + (wn + 16 * nj) * LDH + cb + loff);
                    LDMX4(bfr[2 * nj][0], bfr[2 * nj + 1][0],
                          bfr[2 * nj][1], bfr[2 * nj + 1][1], bd);
                }
#pragma unroll
                for (int mi = 0; mi < 4; mi++)
#pragma unroll
                    for (int ni = 0; ni < 4; ni++) MMA_F16(acc[mi][ni], afr[mi], bfr[ni]);
            }
            stage = (stage + 1) % 3;
        }

        // ---- epilogue for this tile ----
        int m0 = (tile / nx) * BM3, n0 = (tile % nx) * BN3;
        int b = m0 >> 12;
#pragma unroll
        for (int ni = 0; ni < 4; ni++) {
            int col = n0 + wn + ni * 8 + 2 * tig;
            float b0, b1;
            if (EPI == 2) {
                int j = col >> 1;
                b0 = __ldg(bias + j);
                b1 = __ldg(bias + j + MLPH);
            } else {
                b0 = __ldg(bias + col);
                b1 = __ldg(bias + col + 1);
            }
            float g0 = 0.f, g1 = 0.f;
            if (EPI == 1) {
                g0 = __ldg(ch + (size_t)b * D9 + gate_slot * Dx + col);
                g1 = __ldg(ch + (size_t)b * D9 + gate_slot * Dx + col + 1);
            }
#pragma unroll
            for (int mi = 0; mi < 4; mi++) {
                int row = m0 + wm + mi * 16 + g;
#pragma unroll
                for (int hh = 0; hh < 2; hh++) {
                    int rr = row + hh * 8;
                    float v0 = acc[mi][ni][2 * hh] + b0;
                    float v1 = acc[mi][ni][2 * hh + 1] + b1;
                    if (EPI == 0) {
                        st2(C + (size_t)rr * N + col, v0, v1);
                    } else if (EPI == 1) {
                        int orow;
                        if (mode == 0) {
                            orow = rr;
                        } else {
                            int l = (rr >> 4) & 255;
                            int tt = rr & 15;
                            orow = (((rr >> 12) << 4) + tt) * Lx + l;
                        }
                        size_t oi = (size_t)orow * Dx + col;
                        float2 bs = *reinterpret_cast<const float2*>(base + oi);
                        st2((float*)C + oi, bs.x + g0 * v0, bs.y + g1 * v1);
                    } else {
                        float sig = 1.f / (1.f + fexp2(-v0 * 1.44269504f));
                        ((__half*)C)[(size_t)rr * MLPH + (col >> 1)] =
                            __float2half_rn(v0 * sig * v1);
                    }
                }
            }
        }
        tile += G;
    }
#undef ISSUE_PF
}

// ---------------- small fp32 GEMM for the ada projection (M=2) -------------
#define TSZ 64
#define KSZ 16
__global__ void gemm_bias_kernel(const float* __restrict__ A, const float* __restrict__ B,
                                 const float* __restrict__ bias, float* __restrict__ C,
                                 int M, int N, int K) {
    __shared__ float As[KSZ][TSZ];
    __shared__ float Bs[KSZ][TSZ];
    int tx = threadIdx.x, ty = threadIdx.y;
    int tid = ty * 16 + tx;
    int m0 = blockIdx.y * TSZ, n0 = blockIdx.x * TSZ;
    float acc[4][4];
#pragma unroll
    for (int i = 0; i < 4; i++)
#pragma unroll
        for (int j = 0; j < 4; j++) acc[i][j] = 0.f;
    for (int k0 = 0; k0 < K; k0 += KSZ) {
#pragma unroll
        for (int r = 0; r < 4; r++) {
            int e = tid + r * 256;
            int m = e >> 4, k = e & 15;
            int gm = m0 + m;
            As[k][m] = (gm < M) ? A[(size_t)gm * K + k0 + k] : 0.f;
        }
#pragma unroll
        for (int r = 0; r < 4; r++) {
            int e = tid + r * 256;
            int k = e >> 6, n = e & 63;
            Bs[k][n] = B[(size_t)(k0 + k) * N + n0 + n];
        }
        __syncthreads();
#pragma unroll
        for (int kk = 0; kk < KSZ; kk++) {
            float4 a4 = *reinterpret_cast<const float4*>(&As[kk][ty * 4]);
            float4 b4 = *reinterpret_cast<const float4*>(&Bs[kk][tx * 4]);
            float a[4] = {a4.x, a4.y, a4.z, a4.w};
            float b[4] = {b4.x, b4.y, b4.z, b4.w};
#pragma unroll
            for (int i = 0; i < 4; i++)
#pragma unroll
                for (int j = 0; j < 4; j++) acc[i][j] += a[i] * b[j];
        }
        __syncthreads();
    }
#pragma unroll
    for (int i = 0; i < 4; i++) {
        int row = m0 + ty * 4 + i;
        if (row >= M) continue;
        int col = n0 + tx * 4;
        float4 bb = *reinterpret_cast<const float4*>(&bias[col]);
        float4 o;
        o.x = acc[i][0] + bb.x;
        o.y = acc[i][1] + bb.y;
        o.z = acc[i][2] + bb.z;
        o.w = acc[i][3] + bb.w;
        *reinterpret_cast<float4*>(&C[(size_t)row * N + col]) = o;
    }
}

// ---------------- elementwise kernels --------------------------------------
__global__ void silu_c_kernel(const float* __restrict__ c, float* __restrict__ out, int n) {
    int i = blockIdx.x * blockDim.x + threadIdx.x;
    if (i < n) {
        float v = c[i];
        out[i] = v / (1.f + expf(-v));
    }
}

__global__ void modrms_kernel(const float* __restrict__ src, const float* __restrict__ w,
                              const float* __restrict__ ch, int shift_slot, int scale_slot,
                              __half* __restrict__ out, int mode) {
    __shared__ float red[8];
    __shared__ float s_rstd;
    int r = blockIdx.x;
    int b = r >> 12;
    int srow;
    if (mode == 0) {
        srow = r;
    } else {
        int l = (r >> 4) & 255;
        int t = r & 15;
        srow = ((b << 4) + t) * Lx + l;
    }
    const float* xr = src + (size_t)srow * Dx;
    float ss = 0.f;
    for (int d = threadIdx.x; d < Dx; d += 256) {
        float v = xr[d];
        ss += v * v;
    }
#pragma unroll
    for (int o = 16; o; o >>= 1) ss += __shfl_xor_sync(0xffffffffu, ss, o);
    if ((threadIdx.x & 31) == 0) red[threadIdx.x >> 5] = ss;
    __syncthreads();
    if (threadIdx.x == 0) {
        float tot = red[0] + red[1] + red[2] + red[3] + red[4] + red[5] + red[6] + red[7];
        s_rstd = rsqrtf(tot / (float)Dx + 1e-6f);
    }
    __syncthreads();
    float rstd = s_rstd;
    const float* chb = ch + (size_t)b * D9;
    __half* orow = out + (size_t)r * Dx;
    for (int d = threadIdx.x; d < Dx; d += 256) {
        orow[d] = __float2half_rn(xr[d] * rstd * w[d] * (1.f + chb[scale_slot * Dx + d]) +
                                  chb[shift_slot * Dx + d]);
    }
}

// ---------------- spatial attention: FA2-style mma.sync + fused QK-RMS -----
#define QP 88
#define VP 72
#define KBUF (64 * QP)
#define VBUF (72 * VP)
#define TBUF (KBUF + VBUF)
#define AS_SMEM_H (256 * QP)

__global__ __launch_bounds__(256, 1) void attn_s_mma_kernel(
    const __half* __restrict__ qkv, __half* __restrict__ o,
    const float* __restrict__ qn, const float* __restrict__ kn) {
    extern __shared__ __half sm[];
    int seq = blockIdx.x >> 4;
    int h = blockIdx.x & 15;
    int tid = threadIdx.x;
    int wid = tid >> 5, lane = tid & 31;
    int g = lane >> 2, tig = lane & 3;
    int qb = wid * 32;
    const float SC2 = 0.11785113019775793f * 1.4426950408889634f;

    int loffQ = (lane & 15) * QP + (lane >> 4) * 8;
    int loffV = (lane & 15) * VP + (lane >> 4) * 8;

    const __half* gq = qkv + (size_t)seq * 256 * D3 + h * HDx;

    *reinterpret_cast<uint4*>(sm + tid * QP + 72) = make_uint4(0, 0, 0, 0);
#pragma unroll
    for (int r = 0; r < 9; r++) {
        int c = tid + r * 256;
        int row = c / 9, k = c - row * 9;
        CP_ASYNC16(smem_u32(sm + row * QP + 8 * k), gq + (size_t)row * D3 + 8 * k);
    }
    CP_COMMIT();
    CP_WAIT0();
    __syncthreads();

    {
        __half* qrow = sm + tid * QP;
        float ss = 0.f;
#pragma unroll
        for (int d = 0; d < HDx; d++) {
            float v = __half2float(qrow[d]);
            ss += v * v;
        }
        float rstd = rsqrtf(ss * (1.f / HDx) + 1e-6f);
#pragma unroll
        for (int d = 0; d < HDx; d++)
            qrow[d] = __float2half_rn(__half2float(qrow[d]) * rstd * __ldg(qn + d));
    }
    __syncthreads();

    uint32_t qf[2][5][4];
#pragma unroll
    for (int mt = 0; mt < 2; mt++)
#pragma unroll
        for (int kt = 0; kt < 5; kt++) {
            uint32_t ad = smem_u32(sm + (qb + 16 * mt) * QP + 16 * kt + loffQ);
            LDMX4(qf[mt][kt][0], qf[mt][kt][1], qf[mt][kt][2], qf[mt][kt][3], ad);
        }
    __syncthreads();

    {
        __half* Kb = sm;
        __half* Vb = sm + KBUF;
        if (tid < 64) *reinterpret_cast<uint4*>(Kb + tid * QP + 72) = make_uint4(0, 0, 0, 0);
#pragma unroll
        for (int r = 0; r < 3; r++) {
            int c = tid + r * 256;
            if (c < 576) {
                int row = c / 9, k = c - row * 9;
                CP_ASYNC16(smem_u32(Kb + row * QP + 8 * k),
                           gq + Dx + (size_t)row * D3 + 8 * k);
            }
        }
        CP_COMMIT();
#pragma unroll
        for (int r = 0; r < 3; r++) {
            int c = tid + r * 256;
            if (c < 576) {
                int row = c / 9, k = c - row * 9;
                uint4 u = *reinterpret_cast<const uint4*>(gq + 2 * Dx + (size_t)row * D3 + 8 * k);
                __half2 h0 = *reinterpret_cast<__half2*>(&u.x);
                __half2 h1 = *reinterpret_cast<__half2*>(&u.y);
                __half2 h2 = *reinterpret_cast<__half2*>(&u.z);
                __half2 h3 = *reinterpret_cast<__half2*>(&u.w);
                __half* d = Vb + 8 * k * VP + row;
                d[0 * VP] = h0.x; d[1 * VP] = h0.y;
                d[2 * VP] = h1.x; d[3 * VP] = h1.y;
                d[4 * VP] = h2.x; d[5 * VP] = h2.y;
                d[6 * VP] = h3.x; d[7 * VP] = h3.y;
            }
        }
    }

    float oacc[2][9][4];
#pragma unroll
    for (int mt = 0; mt < 2; mt++)
#pragma unroll
        for (int n = 0; n < 9; n++)
#pragma unroll
            for (int r = 0; r < 4; r++) oacc[mt][n][r] = 0.f;
    float lsum[2][2] = {{0.f, 0.f}, {0.f, 0.f}};

#pragma unroll
    for (int jb = 0; jb < 4; jb++) {
        __half* cur = sm + (jb & 1) * TBUF;
        __half* nxt = sm + ((jb & 1) ^ 1) * TBUF;

        uint4 v0, v1, v2;
        if (jb < 3) {
            const __half* gk = gq + Dx + (size_t)(jb + 1) * 64 * D3;
            const __half* gv = gq + 2 * Dx + (size_t)(jb + 1) * 64 * D3;
            if (tid < 64) *reinterpret_cast<uint4*>(nxt + tid * QP + 72) = make_uint4(0, 0, 0, 0);
#pragma unroll
            for (int r = 0; r < 3; r++) {
                int c = tid + r * 256;
                if (c < 576) {
                    int row = c / 9, k = c - row * 9;
                    CP_ASYNC16(smem_u32(nxt + row * QP + 8 * k), gk + (size_t)row * D3 + 8 * k);
                }
            }
            CP_COMMIT();
            {
                int c0 = tid, c1 = tid + 256;
                int r0 = c0 / 9, k0 = c0 - r0 * 9;
                int r1 = c1 / 9, k1 = c1 - r1 * 9;
                v0 = *reinterpret_cast<const uint4*>(gv + (size_t)r0 * D3 + 8 * k0);
                v1 = *reinterpret_cast<const uint4*>(gv + (size_t)r1 * D3 + 8 * k1);
                if (tid < 64) {
                    int c2 = tid + 512;
                    int r2 = c2 / 9, k2 = c2 - r2 * 9;
                    v2 = *reinterpret_cast<const uint4*>(gv + (size_t)r2 * D3 + 8 * k2);
                }
            }
        }
        if (jb < 3) { CP_WAIT1(); } else { CP_WAIT0(); }
        __syncthreads();

        {
            int r = tid >> 2, p = tid & 3;
            __half* krow = cur + r * QP + p * 18;
            float ss = 0.f;
#pragma unroll
            for (int i = 0; i < 18; i++) {
                float v = __half2float(krow[i]);
                ss += v * v;
            }
            ss += __shfl_xor_sync(0xffffffffu, ss, 1);
            ss += __shfl_xor_sync(0xffffffffu, ss, 2);
            float rstd = rsqrtf(ss * (1.f / HDx) + 1e-6f);
#pragma unroll
            for (int i = 0; i < 18; i++)
                krow[i] = __float2half_rn(__half2float(krow[i]) * rstd *
                                          __ldg(kn + p * 18 + i));
        }
        __syncthreads();

        float sacc[8][2][4];
#pragma unroll
        for (int n = 0; n < 8; n++)
#pragma unroll
            for (int mt = 0; mt < 2; mt++)
#pragma unroll
                for (int r = 0; r < 4; r++) sacc[n][mt][r] = 0.f;
#pragma unroll
        for (int kt = 0; kt < 5; kt++) {
            uint32_t bfr[8][2];
#pragma unroll
            for (int jn = 0; jn < 4; jn++) {
                uint32_t bd = smem_u32(cur + (16 * jn) * QP + 16 * kt + loffQ);
                LDMX4(bfr[2 * jn][0], bfr[2 * jn + 1][0],
                      bfr[2 * jn][1], bfr[2 * jn + 1][1], bd);
            }
#pragma unroll
            for (int mt = 0; mt < 2; mt++)
#pragma unroll
                for (int n = 0; n < 8; n++) MMA_F16(sacc[n][mt], qf[mt][kt], bfr[n]);
        }

#pragma unroll
        for (int n = 0; n < 8; n++)
#pragma unroll
            for (int mt = 0; mt < 2; mt++) {
                float p0 = fexp2(sacc[n][mt][0] * SC2);
                float p1 = fexp2(sacc[n][mt][1] * SC2);
                float p2 = fexp2(sacc[n][mt][2] * SC2);
                float p3 = fexp2(sacc[n][mt][3] * SC2);
                sacc[n][mt][0] = p0; sacc[n][mt][1] = p1;
                sacc[n][mt][2] = p2; sacc[n][mt][3] = p3;
                lsum[mt][0] += p0 + p1;
                lsum[mt][1] += p2 + p3;
            }

        if (jb < 3) {
            __half* Vn = nxt + KBUF;
            int c0 = tid, c1 = tid + 256;
#pragma unroll
            for (int pass = 0; pass < 2; pass++) {
                int c = pass ? c1 : c0;
                uint4 u = pass ? v1 : v0;
                int row = c / 9, k = c - row * 9;
                __half2 h0 = *reinterpret_cast<__half2*>(&u.x);
                __half2 h1 = *reinterpret_cast<__half2*>(&u.y);
                __half2 h2 = *reinterpret_cast<__half2*>(&u.z);
                __half2 h3 = *reinterpret_cast<__half2*>(&u.w);
                __half* d = Vn + 8 * k * VP + row;
                d[0 * VP] = h0.x; d[1 * VP] = h0.y;
                d[2 * VP] = h1.x; d[3 * VP] = h1.y;
                d[4 * VP] = h2.x; d[5 * VP] = h2.y;
                d[6 * VP] = h3.x; d[7 * VP] = h3.y;
            }
            if (tid < 64) {
                int c2 = tid + 512;
                int row = c2 / 9, k = c2 - row * 9;
                __half2 h0 = *reinterpret_cast<__half2*>(&v2.x);
                __half2 h1 = *reinterpret_cast<__half2*>(&v2.y);
                __half2 h2 = *reinterpret_cast<__half2*>(&v2.z);
                __half2 h3 = *reinterpret_cast<__half2*>(&v2.w);
                __half* d = Vn + 8 * k * VP + row;
                d[0 * VP] = h0.x; d[1 * VP] = h0.y;
                d[2 * VP] = h1.x; d[3 * VP] = h1.y;
                d[4 * VP] = h2.x; d[5 * VP] = h2.y;
                d[6 * VP] = h3.x; d[7 * VP] = h3.y;
            }
        }

        const __half* Vt = cur + KBUF;
#pragma unroll
        for (int kt2 = 0; kt2 < 4; kt2++) {
            uint32_t bfr[9][2];
#pragma unroll
            for (int vn = 0; vn < 4; vn++) {
                uint32_t bd = smem_u32(Vt + (16 * vn) * VP + 16 * kt2 + loffV);
                LDMX4(bfr[2 * vn][0], bfr[2 * vn + 1][0],
                      bfr[2 * vn][1], bfr[2 * vn + 1][1], bd);
            }
            {
                uint32_t bd = smem_u32(Vt + (64 + (lane & 7)) * VP + 16 * kt2 +
                                       ((lane >> 3) & 1) * 8);
                LDMX2(bfr[8][0], bfr[8][1], bd);
            }
#pragma unroll
            for (int mt = 0; mt < 2; mt++) {
                uint32_t afr[4];
                afr[0] = packh2(sacc[2 * kt2][mt][0], sacc[2 * kt2][mt][1]);
                afr[1] = packh2(sacc[2 * kt2][mt][2], sacc[2 * kt2][mt][3]);
                afr[2] = packh2(sacc[2 * kt2 + 1][mt][0], sacc[2 * kt2 + 1][mt][1]);
                afr[3] = packh2(sacc[2 * kt2 + 1][mt][2], sacc[2 * kt2 + 1][mt][3]);
#pragma unroll
                for (int n = 0; n < 9; n++) MMA_F16(oacc[mt][n], afr, bfr[n]);
            }
        }
        __syncthreads();
    }

#pragma unroll
    for (int mt = 0; mt < 2; mt++)
#pragma unroll
        for (int half = 0; half < 2; half++) {
            float l = lsum[mt][half];
            l += __shfl_xor_sync(0xffffffffu, l, 1);
            l += __shfl_xor_sync(0xffffffffu, l, 2);
            lsum[mt][half] = 1.f / l;
        }
#pragma unroll
    for (int mt = 0; mt < 2; mt++) {
        int row0 = seq * 256 + qb + 16 * mt + g;
        float i0 = lsum[mt][0], i1 = lsum[mt][1];
#pragma unroll
        for (int n = 0; n < 9; n++) {
            int col = h * HDx + 8 * n + 2 * tig;
            st2(o + (size_t)row0 * Dx + col, oacc[mt][n][0] * i0, oacc[mt][n][1] * i0);
            st2(o + (size_t)(row0 + 8) * Dx + col, oacc[mt][n][2] * i1, oacc[mt][n][3] * i1);
        }
    }
}

// temporal attention with fused QK-RMS
__global__ void attn_t_kernel(const __half* __restrict__ qkv, __half* __restrict__ o,
                              const float* __restrict__ qn, const float* __restrict__ kn,
                              float scale) {
    int gid = blockIdx.x * 256 + threadIdx.x;
    int lane = threadIdx.x & 31;
    int qi = gid & 15;
    int pair = gid >> 4;
    int h = pair & 15;
    int seq = pair >> 4;
    const __half* qr = qkv + (size_t)(seq * 16 + qi) * D3 + h * HDx;
    float q[HDx];
    float ssq = 0.f;
#pragma unroll 8
    for (int d = 0; d < HDx; d++) {
        float v = __half2float(qr[d]);
        ssq += v * v;
        q[d] = v;
    }
    float rq = rsqrtf(ssq * (1.f / HDx) + 1e-6f);
#pragma unroll 8
    for (int d = 0; d < HDx; d++) q[d] *= rq * __ldg(qn + d) * __ldg(kn + d);
    {
        const __half* kr = qkv + (size_t)(seq * 16 + qi) * D3 + Dx + h * HDx;
        float ssk = 0.f;
#pragma unroll 8
        for (int d = 0; d < HDx; d++) {
            float v = __half2float(kr[d]);
            ssk += v * v;
        }
        ssq = rsqrtf(ssk * (1.f / HDx) + 1e-6f);
    }
    float s[16];
    float l = 0.f;
#pragma unroll
    for (int j = 0; j < 16; j++) {
        const __half* kr = qkv + (size_t)(seq * 16 + j) * D3 + Dx + h * HDx;
        float dot = 0.f;
#pragma unroll 8
        for (int d = 0; d < HDx; d++) dot += q[d] * __half2float(kr[d]);
        float rk = __shfl_sync(0xffffffffu, ssq, (lane & 16) | j);
        float p = __expf(dot * rk * scale);
        s[j] = p;
        l += p;
    }
    float inv = 1.f / l;
    __half* orow = o + (size_t)(seq * 16 + qi) * Dx + h * HDx;
    for (int d = 0; d < HDx; d++) {
        float acc = 0.f;
#pragma unroll
        for (int j = 0; j < 16; j++)
            acc += s[j] * __half2float(qkv[(size_t)(seq * 16 + j) * D3 + 2 * Dx + h * HDx + d]);
        orow[d] = __float2half_rn(acc * inv);
    }
}

// ------------------------------- launch ------------------------------------
static inline int pgrid(int M, int N) {
    int nt = (M / BM3) * (N / BN3);
    return nt < 296 ? nt : 296;
}

extern "C" void kernel_launch(void* const* d_in, const int* in_sizes, int n_in,
                              void* d_out, int out_size) {
    const float* x        = (const float*)d_in[0];
    const float* c        = (const float*)d_in[1];
    const float* norm1_w  = (const float*)d_in[2];
    const float* norm2_w  = (const float*)d_in[3];
    const float* norm3_w  = (const float*)d_in[4];
    const float* qn_s     = (const float*)d_in[5];
    const float* kn_s     = (const float*)d_in[6];
    const float* qkv_s_w  = (const float*)d_in[7];
    const float* qkv_s_b  = (const float*)d_in[8];
    const float* proj_s_w = (const float*)d_in[9];
    const float* proj_s_b = (const float*)d_in[10];
    const float* qn_t     = (const float*)d_in[11];
    const float* kn_t     = (const float*)d_in[12];
    const float* qkv_t_w  = (const float*)d_in[13];
    const float* qkv_t_b  = (const float*)d_in[14];
    const float* proj_t_w = (const float*)d_in[15];
    const float* proj_t_b = (const float*)d_in[16];
    const float* w12_w    = (const float*)d_in[17];
    const float* w12_b    = (const float*)d_in[18];
    const float* w3_w     = (const float*)d_in[19];
    const float* w3_b     = (const float*)d_in[20];
    const float* ada_w    = (const float*)d_in[21];
    const float* ada_b    = (const float*)d_in[22];
    float* out = (float*)d_out;

    float *p_sc, *p_ch;
    __half *p_xn, *p_bigh, *p_h;
    __half *pw_qkv_s, *pw_qkv_t, *pw_proj_s, *pw_proj_t, *pw_w12, *pw_w3;
    cudaGetSymbolAddress((void**)&p_sc, g_sc);
    cudaGetSymbolAddress((void**)&p_ch, g_ch);
    cudaGetSymbolAddress((void**)&p_xn, g_xn);
    cudaGetSymbolAddress((void**)&p_bigh, g_bigh);
    cudaGetSymbolAddress((void**)&p_h, g_h);
    cudaGetSymbolAddress((void**)&pw_qkv_s, g_wt_qkv_s);
    cudaGetSymbolAddress((void**)&pw_qkv_t, g_wt_qkv_t);
    cudaGetSymbolAddress((void**)&pw_proj_s, g_wt_proj_s);
    cudaGetSymbolAddress((void**)&pw_proj_t, g_wt_proj_t);
    cudaGetSymbolAddress((void**)&pw_w12, g_wt_w12);
    cudaGetSymbolAddress((void**)&pw_w3, g_wt_w3);

    cudaFuncSetAttribute(gemm3_kernel<0, __half>,
                         cudaFuncAttributeMaxDynamicSharedMemorySize, GM3_SMEM);
    cudaFuncSetAttribute(gemm3_kernel<1, float>,
                         cudaFuncAttributeMaxDynamicSharedMemorySize, GM3_SMEM);
    cudaFuncSetAttribute(gemm3_kernel<2, __half>,
                         cudaFuncAttributeMaxDynamicSharedMemorySize, GM3_SMEM);
    cudaFuncSetAttribute(attn_s_mma_kernel, cudaFuncAttributeMaxDynamicSharedMemorySize,
                         AS_SMEM_H * 2);

    cudaStream_t s = 0;
    cudaStream_t s1 = g_ss.s;
    const float scale = 0.11785113019775793f;  // 1/sqrt(72)
    dim3 tb(32, 8);

    // ---- fork side stream for all weight transposes ----
    cudaEventRecord(g_ss.evRoot, s);
    cudaStreamWaitEvent(s1, g_ss.evRoot, 0);
    transpose_h_kernel<<<dim3(D3 / 32, Dx / 32), tb, 0, s1>>>(qkv_s_w, pw_qkv_s, Dx, D3);
    transpose_h_kernel<<<dim3(Dx / 32, Dx / 32), tb, 0, s1>>>(proj_s_w, pw_proj_s, Dx, Dx);
    cudaEventRecord(g_ss.evA, s1);
    transpose_h_kernel<<<dim3(D3 / 32, Dx / 32), tb, 0, s1>>>(qkv_t_w, pw_qkv_t, Dx, D3);
    transpose_h_kernel<<<dim3(Dx / 32, Dx / 32), tb, 0, s1>>>(proj_t_w, pw_proj_t, Dx, Dx);
    transpose_h_il_kernel<<<dim3(2 * MLPH / 32, Dx / 32), tb, 0, s1>>>(w12_w, pw_w12, Dx,
                                                                       2 * MLPH);
    transpose_h_kernel<<<dim3(Dx / 32, MLPH / 32), tb, 0, s1>>>(w3_w, pw_w3, MLPH, Dx);
    cudaEventRecord(g_ss.evB, s1);

    // ---- main chain on stream 0 ----
    silu_c_kernel<<<(Bx * Dx + 255) / 256, 256, 0, s>>>(c, p_sc, Bx * Dx);
    {
        dim3 grid(D9 / TSZ, 1);
        dim3 blk(16, 16);
        gemm_bias_kernel<<<grid, blk, 0, s>>>(p_sc, ada_w, ada_b, p_ch, Bx, D9, Dx);
    }
    modrms_kernel<<<NTOK, 256, 0, s>>>(x, norm1_w, p_ch, 0, 1, p_xn, 0);

    // Stage 1: spatial attention
    cudaStreamWaitEvent(s, g_ss.evA, 0);
    gemm3_kernel<0, __half><<<pgrid(NTOK, D3), 256, GM3_SMEM, s>>>(
        p_xn, pw_qkv_s, qkv_s_b, p_bigh, NTOK, D3, Dx, nullptr, nullptr, 0, 0);
    attn_s_mma_kernel<<<32 * NHx, 256, AS_SMEM_H * 2, s>>>(p_bigh, p_xn, qn_s, kn_s);
    gemm3_kernel<1, float><<<pgrid(NTOK, Dx), 256, GM3_SMEM, s>>>(
        p_xn, pw_proj_s, proj_s_b, out, NTOK, Dx, Dx, x, p_ch, 2, 0);

    // Stage 2: temporal attention
    modrms_kernel<<<NTOK, 256, 0, s>>>(out, norm2_w, p_ch, 3, 4, p_xn, 1);
    cudaStreamWaitEvent(s, g_ss.evB, 0);
    gemm3_kernel<0, __half><<<pgrid(NTOK, D3), 256, GM3_SMEM, s>>>(
        p_xn, pw_qkv_t, qkv_t_b, p_bigh, NTOK, D3, Dx, nullptr, nullptr, 0, 0);
    attn_t_kernel<<<512, 256, 0, s>>>(p_bigh, p_xn, qn_t, kn_t, scale);
    gemm3_kernel<1, float><<<pgrid(NTOK, Dx), 256, GM3_SMEM, s>>>(
        p_xn, pw_proj_t, proj_t_b, out, NTOK, Dx, Dx, out, p_ch, 5, 1);

    // Stage 3: MLP
    modrms_kernel<<<NTOK, 256, 0, s>>>(out, norm3_w, p_ch, 6, 7, p_xn, 0);
    gemm3_kernel<2, __half><<<pgrid(NTOK, 2 * MLPH), 256, GM3_SMEM, s>>>(
        p_xn, pw_w12, w12_b, p_h, NTOK, 2 * MLPH, Dx, nullptr, nullptr, 0, 0);
    gemm3_kernel<1, float><<<pgrid(NTOK, Dx), 256, GM3_SMEM, s>>>(
        p_h, pw_w3, w3_b, out, NTOK, Dx, MLPH, out, p_ch, 8, 0);
}

// round 14
// speedup vs baseline: 1.0325x; 1.0325x over previous
#include <cuda_runtime.h>
#include <cuda_fp16.h>
#include <math.h>
#include <stdint.h>

// Problem constants
#define Bx 2
#define Tx 16
#define Lx 256
#define Dx 1152
#define NHx 16
#define HDx 72
#define MLPH 3072
#define NTOK 8192          // B*T*L
#define D3 3456
#define D9 10368

// ---------------- scratch (device globals) --------------------------------
__device__ float g_ch[Bx * D9];
__device__ __half g_xn[(size_t)NTOK * Dx];
__device__ __half g_bigh[(size_t)NTOK * 2 * MLPH];
__device__ __half g_h[(size_t)NTOK * MLPH];
// transposed (half) weights, [N, K] K-major
__device__ __half g_wt_qkv_s[(size_t)D3 * Dx];
__device__ __half g_wt_qkv_t[(size_t)D3 * Dx];
__device__ __half g_wt_proj_s[(size_t)Dx * Dx];
__device__ __half g_wt_proj_t[(size_t)Dx * Dx];
__device__ __half g_wt_w12[(size_t)2 * MLPH * Dx];
__device__ __half g_wt_w3[(size_t)Dx * MLPH];

// ---------------- side stream + events (load-time init) --------------------
struct SideStream {
    cudaStream_t s;
    cudaEvent_t evRoot, evA, evB;
    SideStream() {
        cudaStreamCreateWithFlags(&s, cudaStreamNonBlocking);
        cudaEventCreateWithFlags(&evRoot, cudaEventDisableTiming);
        cudaEventCreateWithFlags(&evA, cudaEventDisableTiming);
        cudaEventCreateWithFlags(&evB, cudaEventDisableTiming);
    }
};
static SideStream g_ss;

// ---------------- helpers ---------------------------------------------------
__device__ __forceinline__ uint32_t smem_u32(const void* p) {
    return (uint32_t)__cvta_generic_to_shared(p);
}

#define CP_ASYNC16(dst, src) \
    asm volatile("cp.async.cg.shared.global [%0], [%1], 16;" :: "r"(dst), "l"(src) : "memory")
#define CP_COMMIT() asm volatile("cp.async.commit_group;" ::: "memory")
#define CP_WAIT1()  asm volatile("cp.async.wait_group 1;" ::: "memory")
#define CP_WAIT0()  asm volatile("cp.async.wait_group 0;" ::: "memory")

#define MMA_F16(d, a, b) \
    asm volatile( \
        "mma.sync.aligned.m16n8k16.row.col.f32.f16.f16.f32 " \
        "{%0,%1,%2,%3}, {%4,%5,%6,%7}, {%8,%9}, {%0,%1,%2,%3};" \
        : "+f"((d)[0]), "+f"((d)[1]), "+f"((d)[2]), "+f"((d)[3]) \
        : "r"((a)[0]), "r"((a)[1]), "r"((a)[2]), "r"((a)[3]), \
          "r"((b)[0]), "r"((b)[1]))

#define LDMX4(r0, r1, r2, r3, addr) \
    asm volatile("ldmatrix.sync.aligned.m8n8.x4.shared.b16 {%0,%1,%2,%3}, [%4];" \
                 : "=r"(r0), "=r"(r1), "=r"(r2), "=r"(r3) : "r"(addr))
#define LDMX2(r0, r1, addr) \
    asm volatile("ldmatrix.sync.aligned.m8n8.x2.shared.b16 {%0,%1}, [%2];" \
                 : "=r"(r0), "=r"(r1) : "r"(addr))

__device__ __forceinline__ void st2(float* p, float a, float b) {
    *reinterpret_cast<float2*>(p) = make_float2(a, b);
}
__device__ __forceinline__ void st2(__half* p, float a, float b) {
    *reinterpret_cast<__half2*>(p) = __floats2half2_rn(a, b);
}
__device__ __forceinline__ uint32_t packh2(float a, float b) {
    __half2 h = __floats2half2_rn(a, b);
    return *reinterpret_cast<uint32_t*>(&h);
}
__device__ __forceinline__ float fexp2(float y) {
    float t = y + 12582912.f;
    int n = __float_as_int(t) - __float_as_int(12582912.f);
    float f = y - (t - 12582912.f);
    float p = 0.0013333558f;
    p = fmaf(p, f, 0.0096181291f);
    p = fmaf(p, f, 0.0555041087f);
    p = fmaf(p, f, 0.2402265070f);
    p = fmaf(p, f, 0.6931471806f);
    p = fmaf(p, f, 1.0f);
    return __int_as_float(__float_as_int(p) + (n << 23));
}

// ---------------- weight transposes to half --------------------------------
__global__ void transpose_h_kernel(const float* __restrict__ W, __half* __restrict__ Wt,
                                   int K, int N) {
    __shared__ float t[32][33];
    int n0 = blockIdx.x * 32, k0 = blockIdx.y * 32;
#pragma unroll
    for (int r = 0; r < 4; r++)
        t[threadIdx.y + r * 8][threadIdx.x] =
            W[(size_t)(k0 + threadIdx.y + r * 8) * N + n0 + threadIdx.x];
    __syncthreads();
#pragma unroll
    for (int r = 0; r < 4; r++)
        Wt[(size_t)(n0 + threadIdx.y + r * 8) * K + k0 + threadIdx.x] =
            __float2half_rn(t[threadIdx.x][threadIdx.y + r * 8]);
}

__global__ void transpose_h_il_kernel(const float* __restrict__ W, __half* __restrict__ Wt,
                                      int K, int N) {
    __shared__ float t[32][33];
    int n0 = blockIdx.x * 32, k0 = blockIdx.y * 32;
    int nn = n0 + threadIdx.x;
    int src = (nn >> 1) + (nn & 1) * MLPH;
#pragma unroll
    for (int r = 0; r < 4; r++)
        t[threadIdx.y + r * 8][threadIdx.x] =
            W[(size_t)(k0 + threadIdx.y + r * 8) * N + src];
    __syncthreads();
#pragma unroll
    for (int r = 0; r < 4; r++)
        Wt[(size_t)(n0 + threadIdx.y + r * 8) * K + k0 + threadIdx.x] =
            __float2half_rn(t[threadIdx.x][threadIdx.y + r * 8]);
}

// ---------------- fp16 mma.sync GEMM v4 (R12 geometry, restored) ------------
// 128x128x64 block tile, 8 warps x (64x32), 3-stage cp.async, single sync
// per k-step, 2 CTAs/SM. K % 64 == 0.
#define BM3 128
#define BN3 128
#define LDH 72
#define STG3 (256 * LDH)
#define GM3_SMEM (3 * STG3 * 2)

template <int EPI, typename OutT>
__global__ __launch_bounds__(256, 2) void gemm3_kernel(
    const __half* __restrict__ A, const __half* __restrict__ Bt,
    const float* __restrict__ bias, OutT* __restrict__ C,
    int M, int N, int K,
    const float* __restrict__ base, const float* __restrict__ ch,
    int gate_slot, int mode) {
    extern __shared__ __half sh[];
    int tid = threadIdx.x;
    int wid = tid >> 5, lane = tid & 31;
    int g = lane >> 2, tig = lane & 3;
    int m0 = blockIdx.y * BM3, n0 = blockIdx.x * BN3;
    int wm = (wid & 1) * 64, wn = (wid >> 1) * 32;
    int loff = ((lane & 7) + ((lane >> 3) & 1) * 8) * LDH + (lane >> 4) * 8;

    const __half* Ab = A + (size_t)m0 * K;
    const __half* Bb = Bt + (size_t)n0 * K;
    const int kt = K >> 6;

    float acc[4][4][4];
#pragma unroll
    for (int mi = 0; mi < 4; mi++)
#pragma unroll
        for (int ni = 0; ni < 4; ni++)
#pragma unroll
            for (int r = 0; r < 4; r++) acc[mi][ni][r] = 0.f;

    int row8 = tid >> 3, c8 = tid & 7;

#pragma unroll
    for (int t = 0; t < 2; t++) {
        __half* dA = sh + t * STG3;
        __half* dB = dA + 128 * LDH;
        int k0 = t * 64;
#pragma unroll
        for (int r = 0; r < 4; r++) {
            int row = row8 + r * 32;
            CP_ASYNC16(smem_u32(dA + row * LDH + c8 * 8), Ab + (size_t)row * K + k0 + c8 * 8);
            CP_ASYNC16(smem_u32(dB + row * LDH + c8 * 8), Bb + (size_t)row * K + k0 + c8 * 8);
        }
        CP_COMMIT();
    }

    for (int t = 0; t < kt; t++) {
        if (t == kt - 1) { CP_WAIT0(); } else { CP_WAIT1(); }
        __syncthreads();
        if (t + 2 < kt) {
            int s = (t + 2) % 3;
            __half* dA = sh + s * STG3;
            __half* dB = dA + 128 * LDH;
            int k0 = (t + 2) * 64;
#pragma unroll
            for (int r = 0; r < 4; r++) {
                int row = row8 + r * 32;
                CP_ASYNC16(smem_u32(dA + row * LDH + c8 * 8),
                           Ab + (size_t)row * K + k0 + c8 * 8);
                CP_ASYNC16(smem_u32(dB + row * LDH + c8 * 8),
                           Bb + (size_t)row * K + k0 + c8 * 8);
            }
            CP_COMMIT();
        }

        int s = t % 3;
        const __half* tA = sh + s * STG3;
        const __half* tB = tA + 128 * LDH;
#pragma unroll
        for (int kk = 0; kk < 4; kk++) {
            int cb = kk * 16;
            uint32_t afr[4][4];
            uint32_t bfr[4][2];
#pragma unroll
            for (int mi = 0; mi < 4; mi++) {
                uint32_t ad = smem_u32(tA + (wm + 16 * mi) * LDH + cb + loff);
                LDMX4(afr[mi][0], afr[mi][1], afr[mi][2], afr[mi][3], ad);
            }
#pragma unroll
            for (int nj = 0; nj < 2; nj++) {
                uint32_t bd = smem_u32(tB + (wn + 16 * nj) * LDH + cb + loff);
                LDMX4(bfr[2 * nj][0], bfr[2 * nj + 1][0],
                      bfr[2 * nj][1], bfr[2 * nj + 1][1], bd);
            }
#pragma unroll
            for (int mi = 0; mi < 4; mi++)
#pragma unroll
                for (int ni = 0; ni < 4; ni++) MMA_F16(acc[mi][ni], afr[mi], bfr[ni]);
        }
    }

    // ---- epilogue ----
    int b = m0 >> 12;
#pragma unroll
    for (int ni = 0; ni < 4; ni++) {
        int col = n0 + wn + ni * 8 + 2 * tig;
        float b0, b1;
        if (EPI == 2) {
            int j = col >> 1;
            b0 = __ldg(bias + j);
            b1 = __ldg(bias + j + MLPH);
        } else {
            b0 = __ldg(bias + col);
            b1 = __ldg(bias + col + 1);
        }
        float g0 = 0.f, g1 = 0.f;
        if (EPI == 1) {
            g0 = __ldg(ch + (size_t)b * D9 + gate_slot * Dx + col);
            g1 = __ldg(ch + (size_t)b * D9 + gate_slot * Dx + col + 1);
        }
#pragma unroll
        for (int mi = 0; mi < 4; mi++) {
            int row = m0 + wm + mi * 16 + g;
#pragma unroll
            for (int hh = 0; hh < 2; hh++) {
                int rr = row + hh * 8;
                float v0 = acc[mi][ni][2 * hh] + b0;
                float v1 = acc[mi][ni][2 * hh + 1] + b1;
                if (EPI == 0) {
                    st2(C + (size_t)rr * N + col, v0, v1);
                } else if (EPI == 1) {
                    int orow;
                    if (mode == 0) {
                        orow = rr;
                    } else {
                        int l = (rr >> 4) & 255;
                        int tt = rr & 15;
                        orow = (((rr >> 12) << 4) + tt) * Lx + l;
                    }
                    size_t oi = (size_t)orow * Dx + col;
                    float2 bs = *reinterpret_cast<const float2*>(base + oi);
                    st2((float*)C + oi, bs.x + g0 * v0, bs.y + g1 * v1);
                } else {
                    float sig = 1.f / (1.f + fexp2(-v0 * 1.44269504f));
                    ((__half*)C)[(size_t)rr * MLPH + (col >> 1)] =
                        __float2half_rn(v0 * sig * v1);
                }
            }
        }
    }
}

// ---------------- ada projection GEMM with fused silu on A -----------------
#define TSZ 64
#define KSZ 16
__global__ void gemm_bias_silu_kernel(const float* __restrict__ A, const float* __restrict__ B,
                                      const float* __restrict__ bias, float* __restrict__ C,
                                      int M, int N, int K) {
    __shared__ float As[KSZ][TSZ];
    __shared__ float Bs[KSZ][TSZ];
    int tx = threadIdx.x, ty = threadIdx.y;
    int tid = ty * 16 + tx;
    int m0 = blockIdx.y * TSZ, n0 = blockIdx.x * TSZ;
    float acc[4][4];
#pragma unroll
    for (int i = 0; i < 4; i++)
#pragma unroll
        for (int j = 0; j < 4; j++) acc[i][j] = 0.f;
    for (int k0 = 0; k0 < K; k0 += KSZ) {
#pragma unroll
        for (int r = 0; r < 4; r++) {
            int e = tid + r * 256;
            int m = e >> 4, k = e & 15;
            int gm = m0 + m;
            float v = (gm < M) ? A[(size_t)gm * K + k0 + k] : 0.f;
            As[k][m] = v / (1.f + expf(-v));  // silu fused on load
        }
#pragma unroll
        for (int r = 0; r < 4; r++) {
            int e = tid + r * 256;
            int k = e >> 6, n = e & 63;
            Bs[k][n] = B[(size_t)(k0 + k) * N + n0 + n];
        }
        __syncthreads();
#pragma unroll
        for (int kk = 0; kk < KSZ; kk++) {
            float4 a4 = *reinterpret_cast<const float4*>(&As[kk][ty * 4]);
            float4 b4 = *reinterpret_cast<const float4*>(&Bs[kk][tx * 4]);
            float a[4] = {a4.x, a4.y, a4.z, a4.w};
            float b[4] = {b4.x, b4.y, b4.z, b4.w};
#pragma unroll
            for (int i = 0; i < 4; i++)
#pragma unroll
                for (int j = 0; j < 4; j++) acc[i][j] += a[i] * b[j];
        }
        __syncthreads();
    }
#pragma unroll
    for (int i = 0; i < 4; i++) {
        int row = m0 + ty * 4 + i;
        if (row >= M) continue;
        int col = n0 + tx * 4;
        float4 bb = *reinterpret_cast<const float4*>(&bias[col]);
        float4 o;
        o.x = acc[i][0] + bb.x;
        o.y = acc[i][1] + bb.y;
        o.z = acc[i][2] + bb.z;
        o.w = acc[i][3] + bb.w;
        *reinterpret_cast<float4*>(&C[(size_t)row * N + col]) = o;
    }
}

// ---------------- modrms: float4-vectorized, 2-sync reduction ---------------
__global__ void modrms_kernel(const float* __restrict__ src, const float* __restrict__ w,
                              const float* __restrict__ ch, int shift_slot, int scale_slot,
                              __half* __restrict__ out, int mode) {
    __shared__ float red[8];
    __shared__ float s_rstd;
    int r = blockIdx.x;
    int b = r >> 12;
    int srow;
    if (mode == 0) {
        srow = r;
    } else {
        int l = (r >> 4) & 255;
        int t = r & 15;
        srow = ((b << 4) + t) * Lx + l;
    }
    const float4* xr4 = (const float4*)(src + (size_t)srow * Dx);  // 288 float4
    float4 xv[2];
    float ss = 0.f;
#pragma unroll
    for (int i = 0; i < 2; i++) {
        int idx = threadIdx.x + i * 256;
        if (idx < 288) {
            float4 v = xr4[idx];
            xv[i] = v;
            ss += v.x * v.x + v.y * v.y + v.z * v.z + v.w * v.w;
        }
    }
#pragma unroll
    for (int o = 16; o; o >>= 1) ss += __shfl_xor_sync(0xffffffffu, ss, o);
    if ((threadIdx.x & 31) == 0) red[threadIdx.x >> 5] = ss;
    __syncthreads();
    if (threadIdx.x == 0) {
        float tot = red[0] + red[1] + red[2] + red[3] + red[4] + red[5] + red[6] + red[7];
        s_rstd = rsqrtf(tot / (float)Dx + 1e-6f);
    }
    __syncthreads();
    float rstd = s_rstd;
    const float* chb = ch + (size_t)b * D9;
    const float4* sc4 = (const float4*)(chb + scale_slot * Dx);
    const float4* sh4 = (const float4*)(chb + shift_slot * Dx);
    const float4* w4 = (const float4*)w;
    __half2* orow = (__half2*)(out + (size_t)r * Dx);
#pragma unroll
    for (int i = 0; i < 2; i++) {
        int idx = threadIdx.x + i * 256;
        if (idx < 288) {
            float4 v = xv[i];
            float4 wv = w4[idx];
            float4 sc = sc4[idx];
            float4 shv = sh4[idx];
            float o0 = v.x * rstd * wv.x * (1.f + sc.x) + shv.x;
            float o1 = v.y * rstd * wv.y * (1.f + sc.y) + shv.y;
            float o2 = v.z * rstd * wv.z * (1.f + sc.z) + shv.z;
            float o3 = v.w * rstd * wv.w * (1.f + sc.w) + shv.w;
            orow[2 * idx] = __floats2half2_rn(o0, o1);
            orow[2 * idx + 1] = __floats2half2_rn(o2, o3);
        }
    }
}

// ---------------- spatial attention: FA2-style mma.sync + fused QK-RMS -----
#define QP 88
#define VP 72
#define KBUF (64 * QP)
#define VBUF (72 * VP)
#define TBUF (KBUF + VBUF)
#define AS_SMEM_H (256 * QP)

__global__ __launch_bounds__(256, 1) void attn_s_mma_kernel(
    const __half* __restrict__ qkv, __half* __restrict__ o,
    const float* __restrict__ qn, const float* __restrict__ kn) {
    extern __shared__ __half sm[];
    int seq = blockIdx.x >> 4;
    int h = blockIdx.x & 15;
    int tid = threadIdx.x;
    int wid = tid >> 5, lane = tid & 31;
    int g = lane >> 2, tig = lane & 3;
    int qb = wid * 32;
    const float SC2 = 0.11785113019775793f * 1.4426950408889634f;

    int loffQ = (lane & 15) * QP + (lane >> 4) * 8;
    int loffV = (lane & 15) * VP + (lane >> 4) * 8;

    const __half* gq = qkv + (size_t)seq * 256 * D3 + h * HDx;

    *reinterpret_cast<uint4*>(sm + tid * QP + 72) = make_uint4(0, 0, 0, 0);
#pragma unroll
    for (int r = 0; r < 9; r++) {
        int c = tid + r * 256;
        int row = c / 9, k = c - row * 9;
        CP_ASYNC16(smem_u32(sm + row * QP + 8 * k), gq + (size_t)row * D3 + 8 * k);
    }
    CP_COMMIT();
    CP_WAIT0();
    __syncthreads();

    {
        __half* qrow = sm + tid * QP;
        float ss = 0.f;
#pragma unroll
        for (int d = 0; d < HDx; d++) {
            float v = __half2float(qrow[d]);
            ss += v * v;
        }
        float rstd = rsqrtf(ss * (1.f / HDx) + 1e-6f);
#pragma unroll
        for (int d = 0; d < HDx; d++)
            qrow[d] = __float2half_rn(__half2float(qrow[d]) * rstd * __ldg(qn + d));
    }
    __syncthreads();

    uint32_t qf[2][5][4];
#pragma unroll
    for (int mt = 0; mt < 2; mt++)
#pragma unroll
        for (int kt = 0; kt < 5; kt++) {
            uint32_t ad = smem_u32(sm + (qb + 16 * mt) * QP + 16 * kt + loffQ);
            LDMX4(qf[mt][kt][0], qf[mt][kt][1], qf[mt][kt][2], qf[mt][kt][3], ad);
        }
    __syncthreads();

    {
        __half* Kb = sm;
        __half* Vb = sm + KBUF;
        if (tid < 64) *reinterpret_cast<uint4*>(Kb + tid * QP + 72) = make_uint4(0, 0, 0, 0);
#pragma unroll
        for (int r = 0; r < 3; r++) {
            int c = tid + r * 256;
            if (c < 576) {
                int row = c / 9, k = c - row * 9;
                CP_ASYNC16(smem_u32(Kb + row * QP + 8 * k),
                           gq + Dx + (size_t)row * D3 + 8 * k);
            }
        }
        CP_COMMIT();
#pragma unroll
        for (int r = 0; r < 3; r++) {
            int c = tid + r * 256;
            if (c < 576) {
                int row = c / 9, k = c - row * 9;
                uint4 u = *reinterpret_cast<const uint4*>(gq + 2 * Dx + (size_t)row * D3 + 8 * k);
                __half2 h0 = *reinterpret_cast<__half2*>(&u.x);
                __half2 h1 = *reinterpret_cast<__half2*>(&u.y);
                __half2 h2 = *reinterpret_cast<__half2*>(&u.z);
                __half2 h3 = *reinterpret_cast<__half2*>(&u.w);
                __half* d = Vb + 8 * k * VP + row;
                d[0 * VP] = h0.x; d[1 * VP] = h0.y;
                d[2 * VP] = h1.x; d[3 * VP] = h1.y;
                d[4 * VP] = h2.x; d[5 * VP] = h2.y;
                d[6 * VP] = h3.x; d[7 * VP] = h3.y;
            }
        }
    }

    float oacc[2][9][4];
#pragma unroll
    for (int mt = 0; mt < 2; mt++)
#pragma unroll
        for (int n = 0; n < 9; n++)
#pragma unroll
            for (int r = 0; r < 4; r++) oacc[mt][n][r] = 0.f;
    float lsum[2][2] = {{0.f, 0.f}, {0.f, 0.f}};

#pragma unroll
    for (int jb = 0; jb < 4; jb++) {
        __half* cur = sm + (jb & 1) * TBUF;
        __half* nxt = sm + ((jb & 1) ^ 1) * TBUF;

        uint4 v0, v1, v2;
        if (jb < 3) {
            const __half* gk = gq + Dx + (size_t)(jb + 1) * 64 * D3;
            const __half* gv = gq + 2 * Dx + (size_t)(jb + 1) * 64 * D3;
            if (tid < 64) *reinterpret_cast<uint4*>(nxt + tid * QP + 72) = make_uint4(0, 0, 0, 0);
#pragma unroll
            for (int r = 0; r < 3; r++) {
                int c = tid + r * 256;
                if (c < 576) {
                    int row = c / 9, k = c - row * 9;
                    CP_ASYNC16(smem_u32(nxt + row * QP + 8 * k), gk + (size_t)row * D3 + 8 * k);
                }
            }
            CP_COMMIT();
            {
                int c0 = tid, c1 = tid + 256;
                int r0 = c0 / 9, k0 = c0 - r0 * 9;
                int r1 = c1 / 9, k1 = c1 - r1 * 9;
                v0 = *reinterpret_cast<const uint4*>(gv + (size_t)r0 * D3 + 8 * k0);
                v1 = *reinterpret_cast<const uint4*>(gv + (size_t)r1 * D3 + 8 * k1);
                if (tid < 64) {
                    int c2 = tid + 512;
                    int r2 = c2 / 9, k2 = c2 - r2 * 9;
                    v2 = *reinterpret_cast<const uint4*>(gv + (size_t)r2 * D3 + 8 * k2);
                }
            }
        }
        if (jb < 3) { CP_WAIT1(); } else { CP_WAIT0(); }
        __syncthreads();

        {
            int r = tid >> 2, p = tid & 3;
            __half* krow = cur + r * QP + p * 18;
            float ss = 0.f;
#pragma unroll
            for (int i = 0; i < 18; i++) {
                float v = __half2float(krow[i]);
                ss += v * v;
            }
            ss += __shfl_xor_sync(0xffffffffu, ss, 1);
            ss += __shfl_xor_sync(0xffffffffu, ss, 2);
            float rstd = rsqrtf(ss * (1.f / HDx) + 1e-6f);
#pragma unroll
            for (int i = 0; i < 18; i++)
                krow[i] = __float2half_rn(__half2float(krow[i]) * rstd *
                                          __ldg(kn + p * 18 + i));
        }
        __syncthreads();

        float sacc[8][2][4];
#pragma unroll
        for (int n = 0; n < 8; n++)
#pragma unroll
            for (int mt = 0; mt < 2; mt++)
#pragma unroll
                for (int r = 0; r < 4; r++) sacc[n][mt][r] = 0.f;
#pragma unroll
        for (int kt = 0; kt < 5; kt++) {
            uint32_t bfr[8][2];
#pragma unroll
            for (int jn = 0; jn < 4; jn++) {
                uint32_t bd = smem_u32(cur + (16 * jn) * QP + 16 * kt + loffQ);
                LDMX4(bfr[2 * jn][0], bfr[2 * jn + 1][0],
                      bfr[2 * jn][1], bfr[2 * jn + 1][1], bd);
            }
#pragma unroll
            for (int mt = 0; mt < 2; mt++)
#pragma unroll
                for (int n = 0; n < 8; n++) MMA_F16(sacc[n][mt], qf[mt][kt], bfr[n]);
        }

#pragma unroll
        for (int n = 0; n < 8; n++)
#pragma unroll
            for (int mt = 0; mt < 2; mt++) {
                float p0 = fexp2(sacc[n][mt][0] * SC2);
                float p1 = fexp2(sacc[n][mt][1] * SC2);
                float p2 = fexp2(sacc[n][mt][2] * SC2);
                float p3 = fexp2(sacc[n][mt][3] * SC2);
                sacc[n][mt][0] = p0; sacc[n][mt][1] = p1;
                sacc[n][mt][2] = p2; sacc[n][mt][3] = p3;
                lsum[mt][0] += p0 + p1;
                lsum[mt][1] += p2 + p3;
            }

        if (jb < 3) {
            __half* Vn = nxt + KBUF;
            int c0 = tid, c1 = tid + 256;
#pragma unroll
            for (int pass = 0; pass < 2; pass++) {
                int c = pass ? c1 : c0;
                uint4 u = pass ? v1 : v0;
                int row = c / 9, k = c - row * 9;
                __half2 h0 = *reinterpret_cast<__half2*>(&u.x);
                __half2 h1 = *reinterpret_cast<__half2*>(&u.y);
                __half2 h2 = *reinterpret_cast<__half2*>(&u.z);
                __half2 h3 = *reinterpret_cast<__half2*>(&u.w);
                __half* d = Vn + 8 * k * VP + row;
                d[0 * VP] = h0.x; d[1 * VP] = h0.y;
                d[2 * VP] = h1.x; d[3 * VP] = h1.y;
                d[4 * VP] = h2.x; d[5 * VP] = h2.y;
                d[6 * VP] = h3.x; d[7 * VP] = h3.y;
            }
            if (tid < 64) {
                int c2 = tid + 512;
                int row = c2 / 9, k = c2 - row * 9;
                __half2 h0 = *reinterpret_cast<__half2*>(&v2.x);
                __half2 h1 = *reinterpret_cast<__half2*>(&v2.y);
                __half2 h2 = *reinterpret_cast<__half2*>(&v2.z);
                __half2 h3 = *reinterpret_cast<__half2*>(&v2.w);
                __half* d = Vn + 8 * k * VP + row;
                d[0 * VP] = h0.x; d[1 * VP] = h0.y;
                d[2 * VP] = h1.x; d[3 * VP] = h1.y;
                d[4 * VP] = h2.x; d[5 * VP] = h2.y;
                d[6 * VP] = h3.x; d[7 * VP] = h3.y;
            }
        }

        const __half* Vt = cur + KBUF;
#pragma unroll
        for (int kt2 = 0; kt2 < 4; kt2++) {
            uint32_t bfr[9][2];
#pragma unroll
            for (int vn = 0; vn < 4; vn++) {
                uint32_t bd = smem_u32(Vt + (16 * vn) * VP + 16 * kt2 + loffV);
                LDMX4(bfr[2 * vn][0], bfr[2 * vn + 1][0],
                      bfr[2 * vn][1], bfr[2 * vn + 1][1], bd);
            }
            {
                uint32_t bd = smem_u32(Vt + (64 + (lane & 7)) * VP + 16 * kt2 +
                                       ((lane >> 3) & 1) * 8);
                LDMX2(bfr[8][0], bfr[8][1], bd);
            }
#pragma unroll
            for (int mt = 0; mt < 2; mt++) {
                uint32_t afr[4];
                afr[0] = packh2(sacc[2 * kt2][mt][0], sacc[2 * kt2][mt][1]);
                afr[1] = packh2(sacc[2 * kt2][mt][2], sacc[2 * kt2][mt][3]);
                afr[2] = packh2(sacc[2 * kt2 + 1][mt][0], sacc[2 * kt2 + 1][mt][1]);
                afr[3] = packh2(sacc[2 * kt2 + 1][mt][2], sacc[2 * kt2 + 1][mt][3]);
#pragma unroll
                for (int n = 0; n < 9; n++) MMA_F16(oacc[mt][n], afr, bfr[n]);
            }
        }
        __syncthreads();
    }

#pragma unroll
    for (int mt = 0; mt < 2; mt++)
#pragma unroll
        for (int half = 0; half < 2; half++) {
            float l = lsum[mt][half];
            l += __shfl_xor_sync(0xffffffffu, l, 1);
            l += __shfl_xor_sync(0xffffffffu, l, 2);
            lsum[mt][half] = 1.f / l;
        }
#pragma unroll
    for (int mt = 0; mt < 2; mt++) {
        int row0 = seq * 256 + qb + 16 * mt + g;
        float i0 = lsum[mt][0], i1 = lsum[mt][1];
#pragma unroll
        for (int n = 0; n < 9; n++) {
            int col = h * HDx + 8 * n + 2 * tig;
            st2(o + (size_t)row0 * Dx + col, oacc[mt][n][0] * i0, oacc[mt][n][1] * i0);
            st2(o + (size_t)(row0 + 8) * Dx + col, oacc[mt][n][2] * i1, oacc[mt][n][3] * i1);
        }
    }
}

// temporal attention with fused QK-RMS
__global__ void attn_t_kernel(const __half* __restrict__ qkv, __half* __restrict__ o,
                              const float* __restrict__ qn, const float* __restrict__ kn,
                              float scale) {
    int gid = blockIdx.x * 256 + threadIdx.x;
    int lane = threadIdx.x & 31;
    int qi = gid & 15;
    int pair = gid >> 4;
    int h = pair & 15;
    int seq = pair >> 4;
    const __half* qr = qkv + (size_t)(seq * 16 + qi) * D3 + h * HDx;
    float q[HDx];
    float ssq = 0.f;
#pragma unroll 8
    for (int d = 0; d < HDx; d++) {
        float v = __half2float(qr[d]);
        ssq += v * v;
        q[d] = v;
    }
    float rq = rsqrtf(ssq * (1.f / HDx) + 1e-6f);
#pragma unroll 8
    for (int d = 0; d < HDx; d++) q[d] *= rq * __ldg(qn + d) * __ldg(kn + d);
    {
        const __half* kr = qkv + (size_t)(seq * 16 + qi) * D3 + Dx + h * HDx;
        float ssk = 0.f;
#pragma unroll 8
        for (int d = 0; d < HDx; d++) {
            float v = __half2float(kr[d]);
            ssk += v * v;
        }
        ssq = rsqrtf(ssk * (1.f / HDx) + 1e-6f);
    }
    float s[16];
    float l = 0.f;
#pragma unroll
    for (int j = 0; j < 16; j++) {
        const __half* kr = qkv + (size_t)(seq * 16 + j) * D3 + Dx + h * HDx;
        float dot = 0.f;
#pragma unroll 8
        for (int d = 0; d < HDx; d++) dot += q[d] * __half2float(kr[d]);
        float rk = __shfl_sync(0xffffffffu, ssq, (lane & 16) | j);
        float p = __expf(dot * rk * scale);
        s[j] = p;
        l += p;
    }
    float inv = 1.f / l;
    __half* orow = o + (size_t)(seq * 16 + qi) * Dx + h * HDx;
    for (int d = 0; d < HDx; d++) {
        float acc = 0.f;
#pragma unroll
        for (int j = 0; j < 16; j++)
            acc += s[j] * __half2float(qkv[(size_t)(seq * 16 + j) * D3 + 2 * Dx + h * HDx + d]);
        orow[d] = __float2half_rn(acc * inv);
    }
}

// ------------------------------- launch ------------------------------------
extern "C" void kernel_launch(void* const* d_in, const int* in_sizes, int n_in,
                              void* d_out, int out_size) {
    const float* x        = (const float*)d_in[0];
    const float* c        = (const float*)d_in[1];
    const float* norm1_w  = (const float*)d_in[2];
    const float* norm2_w  = (const float*)d_in[3];
    const float* norm3_w  = (const float*)d_in[4];
    const float* qn_s     = (const float*)d_in[5];
    const float* kn_s     = (const float*)d_in[6];
    const float* qkv_s_w  = (const float*)d_in[7];
    const float* qkv_s_b  = (const float*)d_in[8];
    const float* proj_s_w = (const float*)d_in[9];
    const float* proj_s_b = (const float*)d_in[10];
    const float* qn_t     = (const float*)d_in[11];
    const float* kn_t     = (const float*)d_in[12];
    const float* qkv_t_w  = (const float*)d_in[13];
    const float* qkv_t_b  = (const float*)d_in[14];
    const float* proj_t_w = (const float*)d_in[15];
    const float* proj_t_b = (const float*)d_in[16];
    const float* w12_w    = (const float*)d_in[17];
    const float* w12_b    = (const float*)d_in[18];
    const float* w3_w     = (const float*)d_in[19];
    const float* w3_b     = (const float*)d_in[20];
    const float* ada_w    = (const float*)d_in[21];
    const float* ada_b    = (const float*)d_in[22];
    float* out = (float*)d_out;

    float *p_ch;
    __half *p_xn, *p_bigh, *p_h;
    __half *pw_qkv_s, *pw_qkv_t, *pw_proj_s, *pw_proj_t, *pw_w12, *pw_w3;
    cudaGetSymbolAddress((void**)&p_ch, g_ch);
    cudaGetSymbolAddress((void**)&p_xn, g_xn);
    cudaGetSymbolAddress((void**)&p_bigh, g_bigh);
    cudaGetSymbolAddress((void**)&p_h, g_h);
    cudaGetSymbolAddress((void**)&pw_qkv_s, g_wt_qkv_s);
    cudaGetSymbolAddress((void**)&pw_qkv_t, g_wt_qkv_t);
    cudaGetSymbolAddress((void**)&pw_proj_s, g_wt_proj_s);
    cudaGetSymbolAddress((void**)&pw_proj_t, g_wt_proj_t);
    cudaGetSymbolAddress((void**)&pw_w12, g_wt_w12);
    cudaGetSymbolAddress((void**)&pw_w3, g_wt_w3);

    cudaFuncSetAttribute(gemm3_kernel<0, __half>,
                         cudaFuncAttributeMaxDynamicSharedMemorySize, GM3_SMEM);
    cudaFuncSetAttribute(gemm3_kernel<1, float>,
                         cudaFuncAttributeMaxDynamicSharedMemorySize, GM3_SMEM);
    cudaFuncSetAttribute(gemm3_kernel<2, __half>,
                         cudaFuncAttributeMaxDynamicSharedMemorySize, GM3_SMEM);
    cudaFuncSetAttribute(attn_s_mma_kernel, cudaFuncAttributeMaxDynamicSharedMemorySize,
                         AS_SMEM_H * 2);

    cudaStream_t s = 0;
    cudaStream_t s1 = g_ss.s;
    const float scale = 0.11785113019775793f;  // 1/sqrt(72)
    dim3 tb(32, 8);

    // ---- fork side stream for all weight transposes ----
    cudaEventRecord(g_ss.evRoot, s);
    cudaStreamWaitEvent(s1, g_ss.evRoot, 0);
    transpose_h_kernel<<<dim3(D3 / 32, Dx / 32), tb, 0, s1>>>(qkv_s_w, pw_qkv_s, Dx, D3);
    transpose_h_kernel<<<dim3(Dx / 32, Dx / 32), tb, 0, s1>>>(proj_s_w, pw_proj_s, Dx, Dx);
    cudaEventRecord(g_ss.evA, s1);
    transpose_h_kernel<<<dim3(D3 / 32, Dx / 32), tb, 0, s1>>>(qkv_t_w, pw_qkv_t, Dx, D3);
    transpose_h_kernel<<<dim3(Dx / 32, Dx / 32), tb, 0, s1>>>(proj_t_w, pw_proj_t, Dx, Dx);
    transpose_h_il_kernel<<<dim3(2 * MLPH / 32, Dx / 32), tb, 0, s1>>>(w12_w, pw_w12, Dx,
                                                                       2 * MLPH);
    transpose_h_kernel<<<dim3(Dx / 32, MLPH / 32), tb, 0, s1>>>(w3_w, pw_w3, MLPH, Dx);
    cudaEventRecord(g_ss.evB, s1);

    // ---- main chain on stream 0 ----
    {
        dim3 grid(D9 / TSZ, 1);
        dim3 blk(16, 16);
        gemm_bias_silu_kernel<<<grid, blk, 0, s>>>(c, ada_w, ada_b, p_ch, Bx, D9, Dx);
    }
    modrms_kernel<<<NTOK, 256, 0, s>>>(x, norm1_w, p_ch, 0, 1, p_xn, 0);

    // Stage 1: spatial attention
    cudaStreamWaitEvent(s, g_ss.evA, 0);
    gemm3_kernel<0, __half><<<dim3(D3 / BN3, NTOK / BM3), 256, GM3_SMEM, s>>>(
        p_xn, pw_qkv_s, qkv_s_b, p_bigh, NTOK, D3, Dx, nullptr, nullptr, 0, 0);
    attn_s_mma_kernel<<<32 * NHx, 256, AS_SMEM_H * 2, s>>>(p_bigh, p_xn, qn_s, kn_s);
    gemm3_kernel<1, float><<<dim3(Dx / BN3, NTOK / BM3), 256, GM3_SMEM, s>>>(
        p_xn, pw_proj_s, proj_s_b, out, NTOK, Dx, Dx, x, p_ch, 2, 0);

    // Stage 2: temporal attention
    modrms_kernel<<<NTOK, 256, 0, s>>>(out, norm2_w, p_ch, 3, 4, p_xn, 1);
    cudaStreamWaitEvent(s, g_ss.evB, 0);
    gemm3_kernel<0, __half><<<dim3(D3 / BN3, NTOK / BM3), 256, GM3_SMEM, s>>>(
        p_xn, pw_qkv_t, qkv_t_b, p_bigh, NTOK, D3, Dx, nullptr, nullptr, 0, 0);
    attn_t_kernel<<<512, 256, 0, s>>>(p_bigh, p_xn, qn_t, kn_t, scale);
    gemm3_kernel<1, float><<<dim3(Dx / BN3, NTOK / BM3), 256, GM3_SMEM, s>>>(
        p_xn, pw_proj_t, proj_t_b, out, NTOK, Dx, Dx, out, p_ch, 5, 1);

    // Stage 3: MLP
    modrms_kernel<<<NTOK, 256, 0, s>>>(out, norm3_w, p_ch, 6, 7, p_xn, 0);
    gemm3_kernel<2, __half><<<dim3(2 * MLPH / BN3, NTOK / BM3), 256, GM3_SMEM, s>>>(
        p_xn, pw_w12, w12_b, p_h, NTOK, 2 * MLPH, Dx, nullptr, nullptr, 0, 0);
    gemm3_kernel<1, float><<<dim3(Dx / BN3, NTOK / BM3), 256, GM3_SMEM, s>>>(
        p_h, pw_w3, w3_b, out, NTOK, Dx, MLPH, out, p_ch, 8, 0);
}

// round 15
// speedup vs baseline: 1.0994x; 1.0648x over previous
#include <cuda_runtime.h>
#include <cuda_fp16.h>
#include <math.h>
#include <stdint.h>

// Problem constants
#define Bx 2
#define Tx 16
#define Lx 256
#define Dx 1152
#define NHx 16
#define HDx 72
#define MLPH 3072
#define NTOK 8192          // B*T*L
#define D3 3456
#define D9 10368

// ---------------- scratch (device globals) --------------------------------
__device__ float g_ch[Bx * D9];
__device__ __half g_xn[(size_t)NTOK * Dx];
__device__ __half g_bigh[(size_t)NTOK * 2 * MLPH];
__device__ __half g_h[(size_t)NTOK * MLPH];
// transposed (half) weights, [N, K] K-major
__device__ __half g_wt_qkv_s[(size_t)D3 * Dx];
__device__ __half g_wt_qkv_t[(size_t)D3 * Dx];
__device__ __half g_wt_proj_s[(size_t)Dx * Dx];
__device__ __half g_wt_proj_t[(size_t)Dx * Dx];
__device__ __half g_wt_w12[(size_t)2 * MLPH * Dx];
__device__ __half g_wt_w3[(size_t)Dx * MLPH];

// ---------------- side stream + events (load-time init) --------------------
struct SideStream {
    cudaStream_t s;
    cudaEvent_t evRoot, evA, evB;
    SideStream() {
        cudaStreamCreateWithFlags(&s, cudaStreamNonBlocking);
        cudaEventCreateWithFlags(&evRoot, cudaEventDisableTiming);
        cudaEventCreateWithFlags(&evA, cudaEventDisableTiming);
        cudaEventCreateWithFlags(&evB, cudaEventDisableTiming);
    }
};
static SideStream g_ss;

// ---------------- helpers ---------------------------------------------------
__device__ __forceinline__ uint32_t smem_u32(const void* p) {
    return (uint32_t)__cvta_generic_to_shared(p);
}

#define CP_ASYNC16(dst, src) \
    asm volatile("cp.async.cg.shared.global [%0], [%1], 16;" :: "r"(dst), "l"(src) : "memory")
#define CP_COMMIT() asm volatile("cp.async.commit_group;" ::: "memory")
#define CP_WAIT1()  asm volatile("cp.async.wait_group 1;" ::: "memory")
#define CP_WAIT0()  asm volatile("cp.async.wait_group 0;" ::: "memory")

#define MMA_F16(d, a, b) \
    asm volatile( \
        "mma.sync.aligned.m16n8k16.row.col.f32.f16.f16.f32 " \
        "{%0,%1,%2,%3}, {%4,%5,%6,%7}, {%8,%9}, {%0,%1,%2,%3};" \
        : "+f"((d)[0]), "+f"((d)[1]), "+f"((d)[2]), "+f"((d)[3]) \
        : "r"((a)[0]), "r"((a)[1]), "r"((a)[2]), "r"((a)[3]), \
          "r"((b)[0]), "r"((b)[1]))

#define LDMX4(r0, r1, r2, r3, addr) \
    asm volatile("ldmatrix.sync.aligned.m8n8.x4.shared.b16 {%0,%1,%2,%3}, [%4];" \
                 : "=r"(r0), "=r"(r1), "=r"(r2), "=r"(r3) : "r"(addr))
#define LDMX2(r0, r1, addr) \
    asm volatile("ldmatrix.sync.aligned.m8n8.x2.shared.b16 {%0,%1}, [%2];" \
                 : "=r"(r0), "=r"(r1) : "r"(addr))

__device__ __forceinline__ void st2(float* p, float a, float b) {
    *reinterpret_cast<float2*>(p) = make_float2(a, b);
}
__device__ __forceinline__ void st2(__half* p, float a, float b) {
    *reinterpret_cast<__half2*>(p) = __floats2half2_rn(a, b);
}
__device__ __forceinline__ uint32_t packh2(float a, float b) {
    __half2 h = __floats2half2_rn(a, b);
    return *reinterpret_cast<uint32_t*>(&h);
}
__device__ __forceinline__ float fexp2(float y) {
    float t = y + 12582912.f;
    int n = __float_as_int(t) - __float_as_int(12582912.f);
    float f = y - (t - 12582912.f);
    float p = 0.0013333558f;
    p = fmaf(p, f, 0.0096181291f);
    p = fmaf(p, f, 0.0555041087f);
    p = fmaf(p, f, 0.2402265070f);
    p = fmaf(p, f, 0.6931471806f);
    p = fmaf(p, f, 1.0f);
    return __int_as_float(__float_as_int(p) + (n << 23));
}

// ---------------- weight transposes to half --------------------------------
__global__ void transpose_h_kernel(const float* __restrict__ W, __half* __restrict__ Wt,
                                   int K, int N) {
    __shared__ float t[32][33];
    int n0 = blockIdx.x * 32, k0 = blockIdx.y * 32;
#pragma unroll
    for (int r = 0; r < 4; r++)
        t[threadIdx.y + r * 8][threadIdx.x] =
            W[(size_t)(k0 + threadIdx.y + r * 8) * N + n0 + threadIdx.x];
    __syncthreads();
#pragma unroll
    for (int r = 0; r < 4; r++)
        Wt[(size_t)(n0 + threadIdx.y + r * 8) * K + k0 + threadIdx.x] =
            __float2half_rn(t[threadIdx.x][threadIdx.y + r * 8]);
}

__global__ void transpose_h_il_kernel(const float* __restrict__ W, __half* __restrict__ Wt,
                                      int K, int N) {
    __shared__ float t[32][33];
    int n0 = blockIdx.x * 32, k0 = blockIdx.y * 32;
    int nn = n0 + threadIdx.x;
    int src = (nn >> 1) + (nn & 1) * MLPH;
#pragma unroll
    for (int r = 0; r < 4; r++)
        t[threadIdx.y + r * 8][threadIdx.x] =
            W[(size_t)(k0 + threadIdx.y + r * 8) * N + src];
    __syncthreads();
#pragma unroll
    for (int r = 0; r < 4; r++)
        Wt[(size_t)(n0 + threadIdx.y + r * 8) * K + k0 + threadIdx.x] =
            __float2half_rn(t[threadIdx.x][threadIdx.y + r * 8]);
}

// ---------------- fp16 mma.sync GEMM v4 (R12 geometry) ----------------------
#define BM3 128
#define BN3 128
#define LDH 72
#define STG3 (256 * LDH)
#define GM3_SMEM (3 * STG3 * 2)

template <int EPI, typename OutT>
__global__ __launch_bounds__(256, 2) void gemm3_kernel(
    const __half* __restrict__ A, const __half* __restrict__ Bt,
    const float* __restrict__ bias, OutT* __restrict__ C,
    int M, int N, int K,
    const float* __restrict__ base, const float* __restrict__ ch,
    int gate_slot, int mode) {
    extern __shared__ __half sh[];
    int tid = threadIdx.x;
    int wid = tid >> 5, lane = tid & 31;
    int g = lane >> 2, tig = lane & 3;
    int m0 = blockIdx.y * BM3, n0 = blockIdx.x * BN3;
    int wm = (wid & 1) * 64, wn = (wid >> 1) * 32;
    int loff = ((lane & 7) + ((lane >> 3) & 1) * 8) * LDH + (lane >> 4) * 8;

    const __half* Ab = A + (size_t)m0 * K;
    const __half* Bb = Bt + (size_t)n0 * K;
    const int kt = K >> 6;

    float acc[4][4][4];
#pragma unroll
    for (int mi = 0; mi < 4; mi++)
#pragma unroll
        for (int ni = 0; ni < 4; ni++)
#pragma unroll
            for (int r = 0; r < 4; r++) acc[mi][ni][r] = 0.f;

    int row8 = tid >> 3, c8 = tid & 7;

#pragma unroll
    for (int t = 0; t < 2; t++) {
        __half* dA = sh + t * STG3;
        __half* dB = dA + 128 * LDH;
        int k0 = t * 64;
#pragma unroll
        for (int r = 0; r < 4; r++) {
            int row = row8 + r * 32;
            CP_ASYNC16(smem_u32(dA + row * LDH + c8 * 8), Ab + (size_t)row * K + k0 + c8 * 8);
            CP_ASYNC16(smem_u32(dB + row * LDH + c8 * 8), Bb + (size_t)row * K + k0 + c8 * 8);
        }
        CP_COMMIT();
    }

    for (int t = 0; t < kt; t++) {
        if (t == kt - 1) { CP_WAIT0(); } else { CP_WAIT1(); }
        __syncthreads();
        if (t + 2 < kt) {
            int s = (t + 2) % 3;
            __half* dA = sh + s * STG3;
            __half* dB = dA + 128 * LDH;
            int k0 = (t + 2) * 64;
#pragma unroll
            for (int r = 0; r < 4; r++) {
                int row = row8 + r * 32;
                CP_ASYNC16(smem_u32(dA + row * LDH + c8 * 8),
                           Ab + (size_t)row * K + k0 + c8 * 8);
                CP_ASYNC16(smem_u32(dB + row * LDH + c8 * 8),
                           Bb + (size_t)row * K + k0 + c8 * 8);
            }
            CP_COMMIT();
        }

        int s = t % 3;
        const __half* tA = sh + s * STG3;
        const __half* tB = tA + 128 * LDH;
#pragma unroll
        for (int kk = 0; kk < 4; kk++) {
            int cb = kk * 16;
            uint32_t afr[4][4];
            uint32_t bfr[4][2];
#pragma unroll
            for (int mi = 0; mi < 4; mi++) {
                uint32_t ad = smem_u32(tA + (wm + 16 * mi) * LDH + cb + loff);
                LDMX4(afr[mi][0], afr[mi][1], afr[mi][2], afr[mi][3], ad);
            }
#pragma unroll
            for (int nj = 0; nj < 2; nj++) {
                uint32_t bd = smem_u32(tB + (wn + 16 * nj) * LDH + cb + loff);
                LDMX4(bfr[2 * nj][0], bfr[2 * nj + 1][0],
                      bfr[2 * nj][1], bfr[2 * nj + 1][1], bd);
            }
#pragma unroll
            for (int mi = 0; mi < 4; mi++)
#pragma unroll
                for (int ni = 0; ni < 4; ni++) MMA_F16(acc[mi][ni], afr[mi], bfr[ni]);
        }
    }

    // ---- epilogue ----
    int b = m0 >> 12;
#pragma unroll
    for (int ni = 0; ni < 4; ni++) {
        int col = n0 + wn + ni * 8 + 2 * tig;
        float b0, b1;
        if (EPI == 2) {
            int j = col >> 1;
            b0 = __ldg(bias + j);
            b1 = __ldg(bias + j + MLPH);
        } else {
            b0 = __ldg(bias + col);
            b1 = __ldg(bias + col + 1);
        }
        float g0 = 0.f, g1 = 0.f;
        if (EPI == 1) {
            g0 = __ldg(ch + (size_t)b * D9 + gate_slot * Dx + col);
            g1 = __ldg(ch + (size_t)b * D9 + gate_slot * Dx + col + 1);
        }
#pragma unroll
        for (int mi = 0; mi < 4; mi++) {
            int row = m0 + wm + mi * 16 + g;
#pragma unroll
            for (int hh = 0; hh < 2; hh++) {
                int rr = row + hh * 8;
                float v0 = acc[mi][ni][2 * hh] + b0;
                float v1 = acc[mi][ni][2 * hh + 1] + b1;
                if (EPI == 0) {
                    st2(C + (size_t)rr * N + col, v0, v1);
                } else if (EPI == 1) {
                    int orow;
                    if (mode == 0) {
                        orow = rr;
                    } else {
                        int l = (rr >> 4) & 255;
                        int tt = rr & 15;
                        orow = (((rr >> 12) << 4) + tt) * Lx + l;
                    }
                    size_t oi = (size_t)orow * Dx + col;
                    float2 bs = *reinterpret_cast<const float2*>(base + oi);
                    st2((float*)C + oi, bs.x + g0 * v0, bs.y + g1 * v1);
                } else {
                    float sig = 1.f / (1.f + fexp2(-v0 * 1.44269504f));
                    ((__half*)C)[(size_t)rr * MLPH + (col >> 1)] =
                        __float2half_rn(v0 * sig * v1);
                }
            }
        }
    }
}

// ---------------- ada projection GEMM with fused silu on A -----------------
#define TSZ 64
#define KSZ 16
__global__ void gemm_bias_silu_kernel(const float* __restrict__ A, const float* __restrict__ B,
                                      const float* __restrict__ bias, float* __restrict__ C,
                                      int M, int N, int K) {
    __shared__ float As[KSZ][TSZ];
    __shared__ float Bs[KSZ][TSZ];
    int tx = threadIdx.x, ty = threadIdx.y;
    int tid = ty * 16 + tx;
    int m0 = blockIdx.y * TSZ, n0 = blockIdx.x * TSZ;
    float acc[4][4];
#pragma unroll
    for (int i = 0; i < 4; i++)
#pragma unroll
        for (int j = 0; j < 4; j++) acc[i][j] = 0.f;
    for (int k0 = 0; k0 < K; k0 += KSZ) {
#pragma unroll
        for (int r = 0; r < 4; r++) {
            int e = tid + r * 256;
            int m = e >> 4, k = e & 15;
            int gm = m0 + m;
            float v = (gm < M) ? A[(size_t)gm * K + k0 + k] : 0.f;
            As[k][m] = v / (1.f + expf(-v));
        }
#pragma unroll
        for (int r = 0; r < 4; r++) {
            int e = tid + r * 256;
            int k = e >> 6, n = e & 63;
            Bs[k][n] = B[(size_t)(k0 + k) * N + n0 + n];
        }
        __syncthreads();
#pragma unroll
        for (int kk = 0; kk < KSZ; kk++) {
            float4 a4 = *reinterpret_cast<const float4*>(&As[kk][ty * 4]);
            float4 b4 = *reinterpret_cast<const float4*>(&Bs[kk][tx * 4]);
            float a[4] = {a4.x, a4.y, a4.z, a4.w};
            float b[4] = {b4.x, b4.y, b4.z, b4.w};
#pragma unroll
            for (int i = 0; i < 4; i++)
#pragma unroll
                for (int j = 0; j < 4; j++) acc[i][j] += a[i] * b[j];
        }
        __syncthreads();
    }
#pragma unroll
    for (int i = 0; i < 4; i++) {
        int row = m0 + ty * 4 + i;
        if (row >= M) continue;
        int col = n0 + tx * 4;
        float4 bb = *reinterpret_cast<const float4*>(&bias[col]);
        float4 o;
        o.x = acc[i][0] + bb.x;
        o.y = acc[i][1] + bb.y;
        o.z = acc[i][2] + bb.z;
        o.w = acc[i][3] + bb.w;
        *reinterpret_cast<float4*>(&C[(size_t)row * N + col]) = o;
    }
}

// ---------------- modrms (R12 scalar form, 2-sync reduction) ----------------
__global__ void modrms_kernel(const float* __restrict__ src, const float* __restrict__ w,
                              const float* __restrict__ ch, int shift_slot, int scale_slot,
                              __half* __restrict__ out, int mode) {
    __shared__ float red[8];
    __shared__ float s_rstd;
    int r = blockIdx.x;
    int b = r >> 12;
    int srow;
    if (mode == 0) {
        srow = r;
    } else {
        int l = (r >> 4) & 255;
        int t = r & 15;
        srow = ((b << 4) + t) * Lx + l;
    }
    const float* xr = src + (size_t)srow * Dx;
    float ss = 0.f;
    for (int d = threadIdx.x; d < Dx; d += 256) {
        float v = xr[d];
        ss += v * v;
    }
#pragma unroll
    for (int o = 16; o; o >>= 1) ss += __shfl_xor_sync(0xffffffffu, ss, o);
    if ((threadIdx.x & 31) == 0) red[threadIdx.x >> 5] = ss;
    __syncthreads();
    if (threadIdx.x == 0) {
        float tot = red[0] + red[1] + red[2] + red[3] + red[4] + red[5] + red[6] + red[7];
        s_rstd = rsqrtf(tot / (float)Dx + 1e-6f);
    }
    __syncthreads();
    float rstd = s_rstd;
    const float* chb = ch + (size_t)b * D9;
    __half* orow = out + (size_t)r * Dx;
    for (int d = threadIdx.x; d < Dx; d += 256) {
        orow[d] = __float2half_rn(xr[d] * rstd * w[d] * (1.f + chb[scale_slot * Dx + d]) +
                                  chb[shift_slot * Dx + d]);
    }
}

// ---------------- spatial attention (unchanged from R12) --------------------
#define QP 88
#define VP 72
#define KBUF (64 * QP)
#define VBUF (72 * VP)
#define TBUF (KBUF + VBUF)
#define AS_SMEM_H (256 * QP)

__global__ __launch_bounds__(256, 1) void attn_s_mma_kernel(
    const __half* __restrict__ qkv, __half* __restrict__ o,
    const float* __restrict__ qn, const float* __restrict__ kn) {
    extern __shared__ __half sm[];
    int seq = blockIdx.x >> 4;
    int h = blockIdx.x & 15;
    int tid = threadIdx.x;
    int wid = tid >> 5, lane = tid & 31;
    int g = lane >> 2, tig = lane & 3;
    int qb = wid * 32;
    const float SC2 = 0.11785113019775793f * 1.4426950408889634f;

    int loffQ = (lane & 15) * QP + (lane >> 4) * 8;
    int loffV = (lane & 15) * VP + (lane >> 4) * 8;

    const __half* gq = qkv + (size_t)seq * 256 * D3 + h * HDx;

    *reinterpret_cast<uint4*>(sm + tid * QP + 72) = make_uint4(0, 0, 0, 0);
#pragma unroll
    for (int r = 0; r < 9; r++) {
        int c = tid + r * 256;
        int row = c / 9, k = c - row * 9;
        CP_ASYNC16(smem_u32(sm + row * QP + 8 * k), gq + (size_t)row * D3 + 8 * k);
    }
    CP_COMMIT();
    CP_WAIT0();
    __syncthreads();

    {
        __half* qrow = sm + tid * QP;
        float ss = 0.f;
#pragma unroll
        for (int d = 0; d < HDx; d++) {
            float v = __half2float(qrow[d]);
            ss += v * v;
        }
        float rstd = rsqrtf(ss * (1.f / HDx) + 1e-6f);
#pragma unroll
        for (int d = 0; d < HDx; d++)
            qrow[d] = __float2half_rn(__half2float(qrow[d]) * rstd * __ldg(qn + d));
    }
    __syncthreads();

    uint32_t qf[2][5][4];
#pragma unroll
    for (int mt = 0; mt < 2; mt++)
#pragma unroll
        for (int kt = 0; kt < 5; kt++) {
            uint32_t ad = smem_u32(sm + (qb + 16 * mt) * QP + 16 * kt + loffQ);
            LDMX4(qf[mt][kt][0], qf[mt][kt][1], qf[mt][kt][2], qf[mt][kt][3], ad);
        }
    __syncthreads();

    {
        __half* Kb = sm;
        __half* Vb = sm + KBUF;
        if (tid < 64) *reinterpret_cast<uint4*>(Kb + tid * QP + 72) = make_uint4(0, 0, 0, 0);
#pragma unroll
        for (int r = 0; r < 3; r++) {
            int c = tid + r * 256;
            if (c < 576) {
                int row = c / 9, k = c - row * 9;
                CP_ASYNC16(smem_u32(Kb + row * QP + 8 * k),
                           gq + Dx + (size_t)row * D3 + 8 * k);
            }
        }
        CP_COMMIT();
#pragma unroll
        for (int r = 0; r < 3; r++) {
            int c = tid + r * 256;
            if (c < 576) {
                int row = c / 9, k = c - row * 9;
                uint4 u = *reinterpret_cast<const uint4*>(gq + 2 * Dx + (size_t)row * D3 + 8 * k);
                __half2 h0 = *reinterpret_cast<__half2*>(&u.x);
                __half2 h1 = *reinterpret_cast<__half2*>(&u.y);
                __half2 h2 = *reinterpret_cast<__half2*>(&u.z);
                __half2 h3 = *reinterpret_cast<__half2*>(&u.w);
                __half* d = Vb + 8 * k * VP + row;
                d[0 * VP] = h0.x; d[1 * VP] = h0.y;
                d[2 * VP] = h1.x; d[3 * VP] = h1.y;
                d[4 * VP] = h2.x; d[5 * VP] = h2.y;
                d[6 * VP] = h3.x; d[7 * VP] = h3.y;
            }
        }
    }

    float oacc[2][9][4];
#pragma unroll
    for (int mt = 0; mt < 2; mt++)
#pragma unroll
        for (int n = 0; n < 9; n++)
#pragma unroll
            for (int r = 0; r < 4; r++) oacc[mt][n][r] = 0.f;
    float lsum[2][2] = {{0.f, 0.f}, {0.f, 0.f}};

#pragma unroll
    for (int jb = 0; jb < 4; jb++) {
        __half* cur = sm + (jb & 1) * TBUF;
        __half* nxt = sm + ((jb & 1) ^ 1) * TBUF;

        uint4 v0, v1, v2;
        if (jb < 3) {
            const __half* gk = gq + Dx + (size_t)(jb + 1) * 64 * D3;
            const __half* gv = gq + 2 * Dx + (size_t)(jb + 1) * 64 * D3;
            if (tid < 64) *reinterpret_cast<uint4*>(nxt + tid * QP + 72) = make_uint4(0, 0, 0, 0);
#pragma unroll
            for (int r = 0; r < 3; r++) {
                int c = tid + r * 256;
                if (c < 576) {
                    int row = c / 9, k = c - row * 9;
                    CP_ASYNC16(smem_u32(nxt + row * QP + 8 * k), gk + (size_t)row * D3 + 8 * k);
                }
            }
            CP_COMMIT();
            {
                int c0 = tid, c1 = tid + 256;
                int r0 = c0 / 9, k0 = c0 - r0 * 9;
                int r1 = c1 / 9, k1 = c1 - r1 * 9;
                v0 = *reinterpret_cast<const uint4*>(gv + (size_t)r0 * D3 + 8 * k0);
                v1 = *reinterpret_cast<const uint4*>(gv + (size_t)r1 * D3 + 8 * k1);
                if (tid < 64) {
                    int c2 = tid + 512;
                    int r2 = c2 / 9, k2 = c2 - r2 * 9;
                    v2 = *reinterpret_cast<const uint4*>(gv + (size_t)r2 * D3 + 8 * k2);
                }
            }
        }
        if (jb < 3) { CP_WAIT1(); } else { CP_WAIT0(); }
        __syncthreads();

        {
            int r = tid >> 2, p = tid & 3;
            __half* krow = cur + r * QP + p * 18;
            float ss = 0.f;
#pragma unroll
            for (int i = 0; i < 18; i++) {
                float v = __half2float(krow[i]);
                ss += v * v;
            }
            ss += __shfl_xor_sync(0xffffffffu, ss, 1);
            ss += __shfl_xor_sync(0xffffffffu, ss, 2);
            float rstd = rsqrtf(ss * (1.f / HDx) + 1e-6f);
#pragma unroll
            for (int i = 0; i < 18; i++)
                krow[i] = __float2half_rn(__half2float(krow[i]) * rstd *
                                          __ldg(kn + p * 18 + i));
        }
        __syncthreads();

        float sacc[8][2][4];
#pragma unroll
        for (int n = 0; n < 8; n++)
#pragma unroll
            for (int mt = 0; mt < 2; mt++)
#pragma unroll
                for (int r = 0; r < 4; r++) sacc[n][mt][r] = 0.f;
#pragma unroll
        for (int kt = 0; kt < 5; kt++) {
            uint32_t bfr[8][2];
#pragma unroll
            for (int jn = 0; jn < 4; jn++) {
                uint32_t bd = smem_u32(cur + (16 * jn) * QP + 16 * kt + loffQ);
                LDMX4(bfr[2 * jn][0], bfr[2 * jn + 1][0],
                      bfr[2 * jn][1], bfr[2 * jn + 1][1], bd);
            }
#pragma unroll
            for (int mt = 0; mt < 2; mt++)
#pragma unroll
                for (int n = 0; n < 8; n++) MMA_F16(sacc[n][mt], qf[mt][kt], bfr[n]);
        }

#pragma unroll
        for (int n = 0; n < 8; n++)
#pragma unroll
            for (int mt = 0; mt < 2; mt++) {
                float p0 = fexp2(sacc[n][mt][0] * SC2);
                float p1 = fexp2(sacc[n][mt][1] * SC2);
                float p2 = fexp2(sacc[n][mt][2] * SC2);
                float p3 = fexp2(sacc[n][mt][3] * SC2);
                sacc[n][mt][0] = p0; sacc[n][mt][1] = p1;
                sacc[n][mt][2] = p2; sacc[n][mt][3] = p3;
                lsum[mt][0] += p0 + p1;
                lsum[mt][1] += p2 + p3;
            }

        if (jb < 3) {
            __half* Vn = nxt + KBUF;
            int c0 = tid, c1 = tid + 256;
#pragma unroll
            for (int pass = 0; pass < 2; pass++) {
                int c = pass ? c1 : c0;
                uint4 u = pass ? v1 : v0;
                int row = c / 9, k = c - row * 9;
                __half2 h0 = *reinterpret_cast<__half2*>(&u.x);
                __half2 h1 = *reinterpret_cast<__half2*>(&u.y);
                __half2 h2 = *reinterpret_cast<__half2*>(&u.z);
                __half2 h3 = *reinterpret_cast<__half2*>(&u.w);
                __half* d = Vn + 8 * k * VP + row;
                d[0 * VP] = h0.x; d[1 * VP] = h0.y;
                d[2 * VP] = h1.x; d[3 * VP] = h1.y;
                d[4 * VP] = h2.x; d[5 * VP] = h2.y;
                d[6 * VP] = h3.x; d[7 * VP] = h3.y;
            }
            if (tid < 64) {
                int c2 = tid + 512;
                int row = c2 / 9, k = c2 - row * 9;
                __half2 h0 = *reinterpret_cast<__half2*>(&v2.x);
                __half2 h1 = *reinterpret_cast<__half2*>(&v2.y);
                __half2 h2 = *reinterpret_cast<__half2*>(&v2.z);
                __half2 h3 = *reinterpret_cast<__half2*>(&v2.w);
                __half* d = Vn + 8 * k * VP + row;
                d[0 * VP] = h0.x; d[1 * VP] = h0.y;
                d[2 * VP] = h1.x; d[3 * VP] = h1.y;
                d[4 * VP] = h2.x; d[5 * VP] = h2.y;
                d[6 * VP] = h3.x; d[7 * VP] = h3.y;
            }
        }

        const __half* Vt = cur + KBUF;
#pragma unroll
        for (int kt2 = 0; kt2 < 4; kt2++) {
            uint32_t bfr[9][2];
#pragma unroll
            for (int vn = 0; vn < 4; vn++) {
                uint32_t bd = smem_u32(Vt + (16 * vn) * VP + 16 * kt2 + loffV);
                LDMX4(bfr[2 * vn][0], bfr[2 * vn + 1][0],
                      bfr[2 * vn][1], bfr[2 * vn + 1][1], bd);
            }
            {
                uint32_t bd = smem_u32(Vt + (64 + (lane & 7)) * VP + 16 * kt2 +
                                       ((lane >> 3) & 1) * 8);
                LDMX2(bfr[8][0], bfr[8][1], bd);
            }
#pragma unroll
            for (int mt = 0; mt < 2; mt++) {
                uint32_t afr[4];
                afr[0] = packh2(sacc[2 * kt2][mt][0], sacc[2 * kt2][mt][1]);
                afr[1] = packh2(sacc[2 * kt2][mt][2], sacc[2 * kt2][mt][3]);
                afr[2] = packh2(sacc[2 * kt2 + 1][mt][0], sacc[2 * kt2 + 1][mt][1]);
                afr[3] = packh2(sacc[2 * kt2 + 1][mt][2], sacc[2 * kt2 + 1][mt][3]);
#pragma unroll
                for (int n = 0; n < 9; n++) MMA_F16(oacc[mt][n], afr, bfr[n]);
            }
        }
        __syncthreads();
    }

#pragma unroll
    for (int mt = 0; mt < 2; mt++)
#pragma unroll
        for (int half = 0; half < 2; half++) {
            float l = lsum[mt][half];
            l += __shfl_xor_sync(0xffffffffu, l, 1);
            l += __shfl_xor_sync(0xffffffffu, l, 2);
            lsum[mt][half] = 1.f / l;
        }
#pragma unroll
    for (int mt = 0; mt < 2; mt++) {
        int row0 = seq * 256 + qb + 16 * mt + g;
        float i0 = lsum[mt][0], i1 = lsum[mt][1];
#pragma unroll
        for (int n = 0; n < 9; n++) {
            int col = h * HDx + 8 * n + 2 * tig;
            st2(o + (size_t)row0 * Dx + col, oacc[mt][n][0] * i0, oacc[mt][n][1] * i0);
            st2(o + (size_t)(row0 + 8) * Dx + col, oacc[mt][n][2] * i1, oacc[mt][n][3] * i1);
        }
    }
}

// temporal attention with fused QK-RMS, uint4-vectorized loads ---------------
__global__ void attn_t_kernel(const __half* __restrict__ qkv, __half* __restrict__ o,
                              const float* __restrict__ qn, const float* __restrict__ kn,
                              float scale) {
    int gid = blockIdx.x * 256 + threadIdx.x;
    int lane = threadIdx.x & 31;
    int qi = gid & 15;
    int pair = gid >> 4;
    int h = pair & 15;
    int seq = pair >> 4;
    const __half* qr = qkv + (size_t)(seq * 16 + qi) * D3 + h * HDx;
    // q: vectorized load, folded qn*kn*rstd_q
    float q[HDx];
    float ssq = 0.f;
#pragma unroll
    for (int t = 0; t < 9; t++) {
        uint4 u = *reinterpret_cast<const uint4*>(qr + 8 * t);
        const __half2* hp = reinterpret_cast<const __half2*>(&u);
#pragma unroll
        for (int i = 0; i < 4; i++) {
            float2 f = __half22float2(hp[i]);
            q[8 * t + 2 * i] = f.x;
            q[8 * t + 2 * i + 1] = f.y;
            ssq += f.x * f.x + f.y * f.y;
        }
    }
    float rq = rsqrtf(ssq * (1.f / HDx) + 1e-6f);
#pragma unroll
    for (int d = 0; d < HDx; d++) q[d] *= rq * __ldg(qn + d) * __ldg(kn + d);
    // own k-row rms, shared via shfl
    {
        const __half* kr = qkv + (size_t)(seq * 16 + qi) * D3 + Dx + h * HDx;
        float ssk = 0.f;
#pragma unroll
        for (int t = 0; t < 9; t++) {
            uint4 u = *reinterpret_cast<const uint4*>(kr + 8 * t);
            const __half2* hp = reinterpret_cast<const __half2*>(&u);
#pragma unroll
            for (int i = 0; i < 4; i++) {
                float2 f = __half22float2(hp[i]);
                ssk += f.x * f.x + f.y * f.y;
            }
        }
        ssq = rsqrtf(ssk * (1.f / HDx) + 1e-6f);
    }
    float s[16];
    float l = 0.f;
#pragma unroll
    for (int j = 0; j < 16; j++) {
        const __half* kr = qkv + (size_t)(seq * 16 + j) * D3 + Dx + h * HDx;
        float dot = 0.f;
#pragma unroll
        for (int t = 0; t < 9; t++) {
            uint4 u = *reinterpret_cast<const uint4*>(kr + 8 * t);
            const __half2* hp = reinterpret_cast<const __half2*>(&u);
#pragma unroll
            for (int i = 0; i < 4; i++) {
                float2 f = __half22float2(hp[i]);
                dot += q[8 * t + 2 * i] * f.x + q[8 * t + 2 * i + 1] * f.y;
            }
        }
        float rk = __shfl_sync(0xffffffffu, ssq, (lane & 16) | j);
        float p = __expf(dot * rk * scale);
        s[j] = p;
        l += p;
    }
    float inv = 1.f / l;
    __half* orow = o + (size_t)(seq * 16 + qi) * Dx + h * HDx;
    const __half* vbase = qkv + (size_t)(seq * 16) * D3 + 2 * Dx + h * HDx;
#pragma unroll
    for (int t = 0; t < 9; t++) {
        float acc[8] = {0.f, 0.f, 0.f, 0.f, 0.f, 0.f, 0.f, 0.f};
#pragma unroll
        for (int j = 0; j < 16; j++) {
            uint4 u = *reinterpret_cast<const uint4*>(vbase + (size_t)j * D3 + 8 * t);
            const __half2* hp = reinterpret_cast<const __half2*>(&u);
            float sj = s[j];
#pragma unroll
            for (int i = 0; i < 4; i++) {
                float2 f = __half22float2(hp[i]);
                acc[2 * i] += sj * f.x;
                acc[2 * i + 1] += sj * f.y;
            }
        }
        __half2* op = reinterpret_cast<__half2*>(orow + 8 * t);
#pragma unroll
        for (int i = 0; i < 4; i++)
            op[i] = __floats2half2_rn(acc[2 * i] * inv, acc[2 * i + 1] * inv);
    }
}

// ------------------------------- launch ------------------------------------
extern "C" void kernel_launch(void* const* d_in, const int* in_sizes, int n_in,
                              void* d_out, int out_size) {
    const float* x        = (const float*)d_in[0];
    const float* c        = (const float*)d_in[1];
    const float* norm1_w  = (const float*)d_in[2];
    const float* norm2_w  = (const float*)d_in[3];
    const float* norm3_w  = (const float*)d_in[4];
    const float* qn_s     = (const float*)d_in[5];
    const float* kn_s     = (const float*)d_in[6];
    const float* qkv_s_w  = (const float*)d_in[7];
    const float* qkv_s_b  = (const float*)d_in[8];
    const float* proj_s_w = (const float*)d_in[9];
    const float* proj_s_b = (const float*)d_in[10];
    const float* qn_t     = (const float*)d_in[11];
    const float* kn_t     = (const float*)d_in[12];
    const float* qkv_t_w  = (const float*)d_in[13];
    const float* qkv_t_b  = (const float*)d_in[14];
    const float* proj_t_w = (const float*)d_in[15];
    const float* proj_t_b = (const float*)d_in[16];
    const float* w12_w    = (const float*)d_in[17];
    const float* w12_b    = (const float*)d_in[18];
    const float* w3_w     = (const float*)d_in[19];
    const float* w3_b     = (const float*)d_in[20];
    const float* ada_w    = (const float*)d_in[21];
    const float* ada_b    = (const float*)d_in[22];
    float* out = (float*)d_out;

    float *p_ch;
    __half *p_xn, *p_bigh, *p_h;
    __half *pw_qkv_s, *pw_qkv_t, *pw_proj_s, *pw_proj_t, *pw_w12, *pw_w3;
    cudaGetSymbolAddress((void**)&p_ch, g_ch);
    cudaGetSymbolAddress((void**)&p_xn, g_xn);
    cudaGetSymbolAddress((void**)&p_bigh, g_bigh);
    cudaGetSymbolAddress((void**)&p_h, g_h);
    cudaGetSymbolAddress((void**)&pw_qkv_s, g_wt_qkv_s);
    cudaGetSymbolAddress((void**)&pw_qkv_t, g_wt_qkv_t);
    cudaGetSymbolAddress((void**)&pw_proj_s, g_wt_proj_s);
    cudaGetSymbolAddress((void**)&pw_proj_t, g_wt_proj_t);
    cudaGetSymbolAddress((void**)&pw_w12, g_wt_w12);
    cudaGetSymbolAddress((void**)&pw_w3, g_wt_w3);

    cudaFuncSetAttribute(gemm3_kernel<0, __half>,
                         cudaFuncAttributeMaxDynamicSharedMemorySize, GM3_SMEM);
    cudaFuncSetAttribute(gemm3_kernel<1, float>,
                         cudaFuncAttributeMaxDynamicSharedMemorySize, GM3_SMEM);
    cudaFuncSetAttribute(gemm3_kernel<2, __half>,
                         cudaFuncAttributeMaxDynamicSharedMemorySize, GM3_SMEM);
    cudaFuncSetAttribute(attn_s_mma_kernel, cudaFuncAttributeMaxDynamicSharedMemorySize,
                         AS_SMEM_H * 2);

    cudaStream_t s = 0;
    cudaStream_t s1 = g_ss.s;
    const float scale = 0.11785113019775793f;  // 1/sqrt(72)
    dim3 tb(32, 8);

    // ---- fork side stream for all weight transposes ----
    cudaEventRecord(g_ss.evRoot, s);
    cudaStreamWaitEvent(s1, g_ss.evRoot, 0);
    transpose_h_kernel<<<dim3(D3 / 32, Dx / 32), tb, 0, s1>>>(qkv_s_w, pw_qkv_s, Dx, D3);
    transpose_h_kernel<<<dim3(Dx / 32, Dx / 32), tb, 0, s1>>>(proj_s_w, pw_proj_s, Dx, Dx);
    cudaEventRecord(g_ss.evA, s1);
    transpose_h_kernel<<<dim3(D3 / 32, Dx / 32), tb, 0, s1>>>(qkv_t_w, pw_qkv_t, Dx, D3);
    transpose_h_kernel<<<dim3(Dx / 32, Dx / 32), tb, 0, s1>>>(proj_t_w, pw_proj_t, Dx, Dx);
    transpose_h_il_kernel<<<dim3(2 * MLPH / 32, Dx / 32), tb, 0, s1>>>(w12_w, pw_w12, Dx,
                                                                       2 * MLPH);
    transpose_h_kernel<<<dim3(Dx / 32, MLPH / 32), tb, 0, s1>>>(w3_w, pw_w3, MLPH, Dx);
    cudaEventRecord(g_ss.evB, s1);

    // ---- main chain on stream 0 ----
    {
        dim3 grid(D9 / TSZ, 1);
        dim3 blk(16, 16);
        gemm_bias_silu_kernel<<<grid, blk, 0, s>>>(c, ada_w, ada_b, p_ch, Bx, D9, Dx);
    }
    modrms_kernel<<<NTOK, 256, 0, s>>>(x, norm1_w, p_ch, 0, 1, p_xn, 0);

    // Stage 1: spatial attention
    cudaStreamWaitEvent(s, g_ss.evA, 0);
    gemm3_kernel<0, __half><<<dim3(D3 / BN3, NTOK / BM3), 256, GM3_SMEM, s>>>(
        p_xn, pw_qkv_s, qkv_s_b, p_bigh, NTOK, D3, Dx, nullptr, nullptr, 0, 0);
    attn_s_mma_kernel<<<32 * NHx, 256, AS_SMEM_H * 2, s>>>(p_bigh, p_xn, qn_s, kn_s);
    gemm3_kernel<1, float><<<dim3(Dx / BN3, NTOK / BM3), 256, GM3_SMEM, s>>>(
        p_xn, pw_proj_s, proj_s_b, out, NTOK, Dx, Dx, x, p_ch, 2, 0);

    // Stage 2: temporal attention
    modrms_kernel<<<NTOK, 256, 0, s>>>(out, norm2_w, p_ch, 3, 4, p_xn, 1);
    cudaStreamWaitEvent(s, g_ss.evB, 0);
    gemm3_kernel<0, __half><<<dim3(D3 / BN3, NTOK / BM3), 256, GM3_SMEM, s>>>(
        p_xn, pw_qkv_t, qkv_t_b, p_bigh, NTOK, D3, Dx, nullptr, nullptr, 0, 0);
    attn_t_kernel<<<512, 256, 0, s>>>(p_bigh, p_xn, qn_t, kn_t, scale);
    gemm3_kernel<1, float><<<dim3(Dx / BN3, NTOK / BM3), 256, GM3_SMEM, s>>>(
        p_xn, pw_proj_t, proj_t_b, out, NTOK, Dx, Dx, out, p_ch, 5, 1);

    // Stage 3: MLP
    modrms_kernel<<<NTOK, 256, 0, s>>>(out, norm3_w, p_ch, 6, 7, p_xn, 0);
    gemm3_kernel<2, __half><<<dim3(2 * MLPH / BN3, NTOK / BM3), 256, GM3_SMEM, s>>>(
        p_xn, pw_w12, w12_b, p_h, NTOK, 2 * MLPH, Dx, nullptr, nullptr, 0, 0);
    gemm3_kernel<1, float><<<dim3(Dx / BN3, NTOK / BM3), 256, GM3_SMEM, s>>>(
        p_h, pw_w3, w3_b, out, NTOK, Dx, MLPH, out, p_ch, 8, 0);
}

// round 16
// speedup vs baseline: 1.1155x; 1.0146x over previous
#include <cuda_runtime.h>
#include <cuda_fp16.h>
#include <math.h>
#include <stdint.h>

// Problem constants
#define Bx 2
#define Tx 16
#define Lx 256
#define Dx 1152
#define NHx 16
#define HDx 72
#define MLPH 3072
#define NTOK 8192          // B*T*L
#define D3 3456
#define D9 10368

// ---------------- scratch (device globals) --------------------------------
__device__ float g_ch[Bx * D9];
__device__ __half g_xn[(size_t)NTOK * Dx];
__device__ __half g_bigh[(size_t)NTOK * 2 * MLPH];
__device__ __half g_h[(size_t)NTOK * MLPH];
// transposed (half) weights, [N, K] K-major
__device__ __half g_wt_qkv_s[(size_t)D3 * Dx];
__device__ __half g_wt_qkv_t[(size_t)D3 * Dx];
__device__ __half g_wt_proj_s[(size_t)Dx * Dx];
__device__ __half g_wt_proj_t[(size_t)Dx * Dx];
__device__ __half g_wt_w12[(size_t)2 * MLPH * Dx];
__device__ __half g_wt_w3[(size_t)Dx * MLPH];

// ---------------- side stream + events (load-time init) --------------------
struct SideStream {
    cudaStream_t s;
    cudaEvent_t evRoot, evA, evB;
    SideStream() {
        cudaStreamCreateWithFlags(&s, cudaStreamNonBlocking);
        cudaEventCreateWithFlags(&evRoot, cudaEventDisableTiming);
        cudaEventCreateWithFlags(&evA, cudaEventDisableTiming);
        cudaEventCreateWithFlags(&evB, cudaEventDisableTiming);
    }
};
static SideStream g_ss;

// ---------------- helpers ---------------------------------------------------
__device__ __forceinline__ uint32_t smem_u32(const void* p) {
    return (uint32_t)__cvta_generic_to_shared(p);
}

#define CP_ASYNC16(dst, src) \
    asm volatile("cp.async.cg.shared.global [%0], [%1], 16;" :: "r"(dst), "l"(src) : "memory")
#define CP_COMMIT() asm volatile("cp.async.commit_group;" ::: "memory")
#define CP_WAIT1()  asm volatile("cp.async.wait_group 1;" ::: "memory")
#define CP_WAIT0()  asm volatile("cp.async.wait_group 0;" ::: "memory")

#define MMA_F16(d, a, b) \
    asm volatile( \
        "mma.sync.aligned.m16n8k16.row.col.f32.f16.f16.f32 " \
        "{%0,%1,%2,%3}, {%4,%5,%6,%7}, {%8,%9}, {%0,%1,%2,%3};" \
        : "+f"((d)[0]), "+f"((d)[1]), "+f"((d)[2]), "+f"((d)[3]) \
        : "r"((a)[0]), "r"((a)[1]), "r"((a)[2]), "r"((a)[3]), \
          "r"((b)[0]), "r"((b)[1]))

#define LDMX4(r0, r1, r2, r3, addr) \
    asm volatile("ldmatrix.sync.aligned.m8n8.x4.shared.b16 {%0,%1,%2,%3}, [%4];" \
                 : "=r"(r0), "=r"(r1), "=r"(r2), "=r"(r3) : "r"(addr))
#define LDMX2(r0, r1, addr) \
    asm volatile("ldmatrix.sync.aligned.m8n8.x2.shared.b16 {%0,%1}, [%2];" \
                 : "=r"(r0), "=r"(r1) : "r"(addr))

__device__ __forceinline__ void st2(float* p, float a, float b) {
    *reinterpret_cast<float2*>(p) = make_float2(a, b);
}
__device__ __forceinline__ void st2(__half* p, float a, float b) {
    *reinterpret_cast<__half2*>(p) = __floats2half2_rn(a, b);
}
__device__ __forceinline__ uint32_t packh2(float a, float b) {
    __half2 h = __floats2half2_rn(a, b);
    return *reinterpret_cast<uint32_t*>(&h);
}
__device__ __forceinline__ float fexp2(float y) {
    float t = y + 12582912.f;
    int n = __float_as_int(t) - __float_as_int(12582912.f);
    float f = y - (t - 12582912.f);
    float p = 0.0013333558f;
    p = fmaf(p, f, 0.0096181291f);
    p = fmaf(p, f, 0.0555041087f);
    p = fmaf(p, f, 0.2402265070f);
    p = fmaf(p, f, 0.6931471806f);
    p = fmaf(p, f, 1.0f);
    return __int_as_float(__float_as_int(p) + (n << 23));
}

// ---------------- weight transposes to half --------------------------------
__global__ void transpose_h_kernel(const float* __restrict__ W, __half* __restrict__ Wt,
                                   int K, int N) {
    __shared__ float t[32][33];
    int n0 = blockIdx.x * 32, k0 = blockIdx.y * 32;
#pragma unroll
    for (int r = 0; r < 4; r++)
        t[threadIdx.y + r * 8][threadIdx.x] =
            W[(size_t)(k0 + threadIdx.y + r * 8) * N + n0 + threadIdx.x];
    __syncthreads();
#pragma unroll
    for (int r = 0; r < 4; r++)
        Wt[(size_t)(n0 + threadIdx.y + r * 8) * K + k0 + threadIdx.x] =
            __float2half_rn(t[threadIdx.x][threadIdx.y + r * 8]);
}

__global__ void transpose_h_il_kernel(const float* __restrict__ W, __half* __restrict__ Wt,
                                      int K, int N) {
    __shared__ float t[32][33];
    int n0 = blockIdx.x * 32, k0 = blockIdx.y * 32;
    int nn = n0 + threadIdx.x;
    int src = (nn >> 1) + (nn & 1) * MLPH;
#pragma unroll
    for (int r = 0; r < 4; r++)
        t[threadIdx.y + r * 8][threadIdx.x] =
            W[(size_t)(k0 + threadIdx.y + r * 8) * N + src];
    __syncthreads();
#pragma unroll
    for (int r = 0; r < 4; r++)
        Wt[(size_t)(n0 + threadIdx.y + r * 8) * K + k0 + threadIdx.x] =
            __float2half_rn(t[threadIdx.x][threadIdx.y + r * 8]);
}

// ---------------- fp16 mma.sync GEMM v4 (R12 geometry) ----------------------
#define BM3 128
#define BN3 128
#define LDH 72
#define STG3 (256 * LDH)
#define GM3_SMEM (3 * STG3 * 2)

template <int EPI, typename OutT>
__global__ __launch_bounds__(256, 2) void gemm3_kernel(
    const __half* __restrict__ A, const __half* __restrict__ Bt,
    const float* __restrict__ bias, OutT* __restrict__ C,
    int M, int N, int K,
    const float* __restrict__ base, const float* __restrict__ ch,
    int gate_slot, int mode) {
    extern __shared__ __half sh[];
    int tid = threadIdx.x;
    int wid = tid >> 5, lane = tid & 31;
    int g = lane >> 2, tig = lane & 3;
    int m0 = blockIdx.y * BM3, n0 = blockIdx.x * BN3;
    int wm = (wid & 1) * 64, wn = (wid >> 1) * 32;
    int loff = ((lane & 7) + ((lane >> 3) & 1) * 8) * LDH + (lane >> 4) * 8;

    const __half* Ab = A + (size_t)m0 * K;
    const __half* Bb = Bt + (size_t)n0 * K;
    const int kt = K >> 6;

    float acc[4][4][4];
#pragma unroll
    for (int mi = 0; mi < 4; mi++)
#pragma unroll
        for (int ni = 0; ni < 4; ni++)
#pragma unroll
            for (int r = 0; r < 4; r++) acc[mi][ni][r] = 0.f;

    int row8 = tid >> 3, c8 = tid & 7;

#pragma unroll
    for (int t = 0; t < 2; t++) {
        __half* dA = sh + t * STG3;
        __half* dB = dA + 128 * LDH;
        int k0 = t * 64;
#pragma unroll
        for (int r = 0; r < 4; r++) {
            int row = row8 + r * 32;
            CP_ASYNC16(smem_u32(dA + row * LDH + c8 * 8), Ab + (size_t)row * K + k0 + c8 * 8);
            CP_ASYNC16(smem_u32(dB + row * LDH + c8 * 8), Bb + (size_t)row * K + k0 + c8 * 8);
        }
        CP_COMMIT();
    }

    for (int t = 0; t < kt; t++) {
        if (t == kt - 1) { CP_WAIT0(); } else { CP_WAIT1(); }
        __syncthreads();
        if (t + 2 < kt) {
            int s = (t + 2) % 3;
            __half* dA = sh + s * STG3;
            __half* dB = dA + 128 * LDH;
            int k0 = (t + 2) * 64;
#pragma unroll
            for (int r = 0; r < 4; r++) {
                int row = row8 + r * 32;
                CP_ASYNC16(smem_u32(dA + row * LDH + c8 * 8),
                           Ab + (size_t)row * K + k0 + c8 * 8);
                CP_ASYNC16(smem_u32(dB + row * LDH + c8 * 8),
                           Bb + (size_t)row * K + k0 + c8 * 8);
            }
            CP_COMMIT();
        }

        int s = t % 3;
        const __half* tA = sh + s * STG3;
        const __half* tB = tA + 128 * LDH;
#pragma unroll
        for (int kk = 0; kk < 4; kk++) {
            int cb = kk * 16;
            uint32_t afr[4][4];
            uint32_t bfr[4][2];
#pragma unroll
            for (int mi = 0; mi < 4; mi++) {
                uint32_t ad = smem_u32(tA + (wm + 16 * mi) * LDH + cb + loff);
                LDMX4(afr[mi][0], afr[mi][1], afr[mi][2], afr[mi][3], ad);
            }
#pragma unroll
            for (int nj = 0; nj < 2; nj++) {
                uint32_t bd = smem_u32(tB + (wn + 16 * nj) * LDH + cb + loff);
                LDMX4(bfr[2 * nj][0], bfr[2 * nj + 1][0],
                      bfr[2 * nj][1], bfr[2 * nj + 1][1], bd);
            }
#pragma unroll
            for (int mi = 0; mi < 4; mi++)
#pragma unroll
                for (int ni = 0; ni < 4; ni++) MMA_F16(acc[mi][ni], afr[mi], bfr[ni]);
        }
    }

    // ---- epilogue ----
    int b = m0 >> 12;
#pragma unroll
    for (int ni = 0; ni < 4; ni++) {
        int col = n0 + wn + ni * 8 + 2 * tig;
        float b0, b1;
        if (EPI == 2) {
            int j = col >> 1;
            b0 = __ldg(bias + j);
            b1 = __ldg(bias + j + MLPH);
        } else {
            b0 = __ldg(bias + col);
            b1 = __ldg(bias + col + 1);
        }
        float g0 = 0.f, g1 = 0.f;
        if (EPI == 1) {
            g0 = __ldg(ch + (size_t)b * D9 + gate_slot * Dx + col);
            g1 = __ldg(ch + (size_t)b * D9 + gate_slot * Dx + col + 1);
        }
#pragma unroll
        for (int mi = 0; mi < 4; mi++) {
            int row = m0 + wm + mi * 16 + g;
#pragma unroll
            for (int hh = 0; hh < 2; hh++) {
                int rr = row + hh * 8;
                float v0 = acc[mi][ni][2 * hh] + b0;
                float v1 = acc[mi][ni][2 * hh + 1] + b1;
                if (EPI == 0) {
                    st2(C + (size_t)rr * N + col, v0, v1);
                } else if (EPI == 1) {
                    int orow;
                    if (mode == 0) {
                        orow = rr;
                    } else {
                        int l = (rr >> 4) & 255;
                        int tt = rr & 15;
                        orow = (((rr >> 12) << 4) + tt) * Lx + l;
                    }
                    size_t oi = (size_t)orow * Dx + col;
                    float2 bs = *reinterpret_cast<const float2*>(base + oi);
                    st2((float*)C + oi, bs.x + g0 * v0, bs.y + g1 * v1);
                } else {
                    float sig = 1.f / (1.f + fexp2(-v0 * 1.44269504f));
                    ((__half*)C)[(size_t)rr * MLPH + (col >> 1)] =
                        __float2half_rn(v0 * sig * v1);
                }
            }
        }
    }
}

// ---------------- ada projection GEMM with fused silu on A -----------------
#define TSZ 64
#define KSZ 16
__global__ void gemm_bias_silu_kernel(const float* __restrict__ A, const float* __restrict__ B,
                                      const float* __restrict__ bias, float* __restrict__ C,
                                      int M, int N, int K) {
    __shared__ float As[KSZ][TSZ];
    __shared__ float Bs[KSZ][TSZ];
    int tx = threadIdx.x, ty = threadIdx.y;
    int tid = ty * 16 + tx;
    int m0 = blockIdx.y * TSZ, n0 = blockIdx.x * TSZ;
    float acc[4][4];
#pragma unroll
    for (int i = 0; i < 4; i++)
#pragma unroll
        for (int j = 0; j < 4; j++) acc[i][j] = 0.f;
    for (int k0 = 0; k0 < K; k0 += KSZ) {
#pragma unroll
        for (int r = 0; r < 4; r++) {
            int e = tid + r * 256;
            int m = e >> 4, k = e & 15;
            int gm = m0 + m;
            float v = (gm < M) ? A[(size_t)gm * K + k0 + k] : 0.f;
            As[k][m] = v / (1.f + expf(-v));
        }
#pragma unroll
        for (int r = 0; r < 4; r++) {
            int e = tid + r * 256;
            int k = e >> 6, n = e & 63;
            Bs[k][n] = B[(size_t)(k0 + k) * N + n0 + n];
        }
        __syncthreads();
#pragma unroll
        for (int kk = 0; kk < KSZ; kk++) {
            float4 a4 = *reinterpret_cast<const float4*>(&As[kk][ty * 4]);
            float4 b4 = *reinterpret_cast<const float4*>(&Bs[kk][tx * 4]);
            float a[4] = {a4.x, a4.y, a4.z, a4.w};
            float b[4] = {b4.x, b4.y, b4.z, b4.w};
#pragma unroll
            for (int i = 0; i < 4; i++)
#pragma unroll
                for (int j = 0; j < 4; j++) acc[i][j] += a[i] * b[j];
        }
        __syncthreads();
    }
#pragma unroll
    for (int i = 0; i < 4; i++) {
        int row = m0 + ty * 4 + i;
        if (row >= M) continue;
        int col = n0 + tx * 4;
        float4 bb = *reinterpret_cast<const float4*>(&bias[col]);
        float4 o;
        o.x = acc[i][0] + bb.x;
        o.y = acc[i][1] + bb.y;
        o.z = acc[i][2] + bb.z;
        o.w = acc[i][3] + bb.w;
        *reinterpret_cast<float4*>(&C[(size_t)row * N + col]) = o;
    }
}

// ---------------- modrms (scalar form, 2-sync reduction) --------------------
__global__ void modrms_kernel(const float* __restrict__ src, const float* __restrict__ w,
                              const float* __restrict__ ch, int shift_slot, int scale_slot,
                              __half* __restrict__ out, int mode) {
    __shared__ float red[8];
    __shared__ float s_rstd;
    int r = blockIdx.x;
    int b = r >> 12;
    int srow;
    if (mode == 0) {
        srow = r;
    } else {
        int l = (r >> 4) & 255;
        int t = r & 15;
        srow = ((b << 4) + t) * Lx + l;
    }
    const float* xr = src + (size_t)srow * Dx;
    float ss = 0.f;
    for (int d = threadIdx.x; d < Dx; d += 256) {
        float v = xr[d];
        ss += v * v;
    }
#pragma unroll
    for (int o = 16; o; o >>= 1) ss += __shfl_xor_sync(0xffffffffu, ss, o);
    if ((threadIdx.x & 31) == 0) red[threadIdx.x >> 5] = ss;
    __syncthreads();
    if (threadIdx.x == 0) {
        float tot = red[0] + red[1] + red[2] + red[3] + red[4] + red[5] + red[6] + red[7];
        s_rstd = rsqrtf(tot / (float)Dx + 1e-6f);
    }
    __syncthreads();
    float rstd = s_rstd;
    const float* chb = ch + (size_t)b * D9;
    __half* orow = out + (size_t)r * Dx;
    for (int d = threadIdx.x; d < Dx; d += 256) {
        orow[d] = __float2half_rn(xr[d] * rstd * w[d] * (1.f + chb[scale_slot * Dx + d]) +
                                  chb[shift_slot * Dx + d]);
    }
}

// ---------------- spatial attention: kn folded into Q, rk post-MMA ---------
#define QP 88
#define VP 72
#define KBUF (64 * QP)
#define VBUF (72 * VP)
#define TBUF (KBUF + VBUF)
#define AS_SMEM_H (256 * QP)

__global__ __launch_bounds__(256, 1) void attn_s_mma_kernel(
    const __half* __restrict__ qkv, __half* __restrict__ o,
    const float* __restrict__ qn, const float* __restrict__ kn) {
    extern __shared__ __half sm[];
    __shared__ float rks[2][64];
    int seq = blockIdx.x >> 4;
    int h = blockIdx.x & 15;
    int tid = threadIdx.x;
    int wid = tid >> 5, lane = tid & 31;
    int g = lane >> 2, tig = lane & 3;
    int qb = wid * 32;
    const float SC2 = 0.11785113019775793f * 1.4426950408889634f;  // scale*log2e

    int loffQ = (lane & 15) * QP + (lane >> 4) * 8;
    int loffV = (lane & 15) * VP + (lane >> 4) * 8;

    const __half* gq = qkv + (size_t)seq * 256 * D3 + h * HDx;

    *reinterpret_cast<uint4*>(sm + tid * QP + 72) = make_uint4(0, 0, 0, 0);
#pragma unroll
    for (int r = 0; r < 9; r++) {
        int c = tid + r * 256;
        int row = c / 9, k = c - row * 9;
        CP_ASYNC16(smem_u32(sm + row * QP + 8 * k), gq + (size_t)row * D3 + 8 * k);
    }
    CP_COMMIT();
    CP_WAIT0();
    __syncthreads();

    // fused Q RMS-norm with kn folded in (one thread per row)
    {
        __half* qrow = sm + tid * QP;
        float ss = 0.f;
#pragma unroll
        for (int d = 0; d < HDx; d++) {
            float v = __half2float(qrow[d]);
            ss += v * v;
        }
        float rstd = rsqrtf(ss * (1.f / HDx) + 1e-6f);
#pragma unroll
        for (int d = 0; d < HDx; d++)
            qrow[d] = __float2half_rn(__half2float(qrow[d]) * rstd * __ldg(qn + d) *
                                      __ldg(kn + d));
    }
    __syncthreads();

    uint32_t qf[2][5][4];
#pragma unroll
    for (int mt = 0; mt < 2; mt++)
#pragma unroll
        for (int kt = 0; kt < 5; kt++) {
            uint32_t ad = smem_u32(sm + (qb + 16 * mt) * QP + 16 * kt + loffQ);
            LDMX4(qf[mt][kt][0], qf[mt][kt][1], qf[mt][kt][2], qf[mt][kt][3], ad);
        }
    __syncthreads();

    {
        __half* Kb = sm;
        __half* Vb = sm + KBUF;
        if (tid < 64) *reinterpret_cast<uint4*>(Kb + tid * QP + 72) = make_uint4(0, 0, 0, 0);
#pragma unroll
        for (int r = 0; r < 3; r++) {
            int c = tid + r * 256;
            if (c < 576) {
                int row = c / 9, k = c - row * 9;
                CP_ASYNC16(smem_u32(Kb + row * QP + 8 * k),
                           gq + Dx + (size_t)row * D3 + 8 * k);
            }
        }
        CP_COMMIT();
#pragma unroll
        for (int r = 0; r < 3; r++) {
            int c = tid + r * 256;
            if (c < 576) {
                int row = c / 9, k = c - row * 9;
                uint4 u = *reinterpret_cast<const uint4*>(gq + 2 * Dx + (size_t)row * D3 + 8 * k);
                __half2 h0 = *reinterpret_cast<__half2*>(&u.x);
                __half2 h1 = *reinterpret_cast<__half2*>(&u.y);
                __half2 h2 = *reinterpret_cast<__half2*>(&u.z);
                __half2 h3 = *reinterpret_cast<__half2*>(&u.w);
                __half* d = Vb + 8 * k * VP + row;
                d[0 * VP] = h0.x; d[1 * VP] = h0.y;
                d[2 * VP] = h1.x; d[3 * VP] = h1.y;
                d[4 * VP] = h2.x; d[5 * VP] = h2.y;
                d[6 * VP] = h3.x; d[7 * VP] = h3.y;
            }
        }
    }

    float oacc[2][9][4];
#pragma unroll
    for (int mt = 0; mt < 2; mt++)
#pragma unroll
        for (int n = 0; n < 9; n++)
#pragma unroll
            for (int r = 0; r < 4; r++) oacc[mt][n][r] = 0.f;
    float lsum[2][2] = {{0.f, 0.f}, {0.f, 0.f}};

#pragma unroll
    for (int jb = 0; jb < 4; jb++) {
        __half* cur = sm + (jb & 1) * TBUF;
        __half* nxt = sm + ((jb & 1) ^ 1) * TBUF;

        uint4 v0, v1, v2;
        if (jb < 3) {
            const __half* gk = gq + Dx + (size_t)(jb + 1) * 64 * D3;
            const __half* gv = gq + 2 * Dx + (size_t)(jb + 1) * 64 * D3;
            if (tid < 64) *reinterpret_cast<uint4*>(nxt + tid * QP + 72) = make_uint4(0, 0, 0, 0);
#pragma unroll
            for (int r = 0; r < 3; r++) {
                int c = tid + r * 256;
                if (c < 576) {
                    int row = c / 9, k = c - row * 9;
                    CP_ASYNC16(smem_u32(nxt + row * QP + 8 * k), gk + (size_t)row * D3 + 8 * k);
                }
            }
            CP_COMMIT();
            {
                int c0 = tid, c1 = tid + 256;
                int r0 = c0 / 9, k0 = c0 - r0 * 9;
                int r1 = c1 / 9, k1 = c1 - r1 * 9;
                v0 = *reinterpret_cast<const uint4*>(gv + (size_t)r0 * D3 + 8 * k0);
                v1 = *reinterpret_cast<const uint4*>(gv + (size_t)r1 * D3 + 8 * k1);
                if (tid < 64) {
                    int c2 = tid + 512;
                    int r2 = c2 / 9, k2 = c2 - r2 * 9;
                    v2 = *reinterpret_cast<const uint4*>(gv + (size_t)r2 * D3 + 8 * k2);
                }
            }
        }
        if (jb < 3) { CP_WAIT1(); } else { CP_WAIT0(); }
        __syncthreads();

        // per-row K rstd only (no K rewrite); rk = rstd * SC2
        {
            int r = tid >> 2, p = tid & 3;
            const __half* krow = cur + r * QP + p * 18;
            float ss = 0.f;
#pragma unroll
            for (int i = 0; i < 18; i++) {
                float v = __half2float(krow[i]);
                ss += v * v;
            }
            ss += __shfl_xor_sync(0xffffffffu, ss, 1);
            ss += __shfl_xor_sync(0xffffffffu, ss, 2);
            if (p == 0) rks[jb & 1][r] = rsqrtf(ss * (1.f / HDx) + 1e-6f) * SC2;
        }
        __syncthreads();

        float sacc[8][2][4];
#pragma unroll
        for (int n = 0; n < 8; n++)
#pragma unroll
            for (int mt = 0; mt < 2; mt++)
#pragma unroll
                for (int r = 0; r < 4; r++) sacc[n][mt][r] = 0.f;
#pragma unroll
        for (int kt = 0; kt < 5; kt++) {
            uint32_t bfr[8][2];
#pragma unroll
            for (int jn = 0; jn < 4; jn++) {
                uint32_t bd = smem_u32(cur + (16 * jn) * QP + 16 * kt + loffQ);
                LDMX4(bfr[2 * jn][0], bfr[2 * jn + 1][0],
                      bfr[2 * jn][1], bfr[2 * jn + 1][1], bd);
            }
#pragma unroll
            for (int mt = 0; mt < 2; mt++)
#pragma unroll
                for (int n = 0; n < 8; n++) MMA_F16(sacc[n][mt], qf[mt][kt], bfr[n]);
        }

        // softmax with per-column rk applied post-MMA
#pragma unroll
        for (int n = 0; n < 8; n++) {
            float rk0 = rks[jb & 1][8 * n + 2 * tig];
            float rk1 = rks[jb & 1][8 * n + 2 * tig + 1];
#pragma unroll
            for (int mt = 0; mt < 2; mt++) {
                float p0 = fexp2(sacc[n][mt][0] * rk0);
                float p1 = fexp2(sacc[n][mt][1] * rk1);
                float p2 = fexp2(sacc[n][mt][2] * rk0);
                float p3 = fexp2(sacc[n][mt][3] * rk1);
                sacc[n][mt][0] = p0; sacc[n][mt][1] = p1;
                sacc[n][mt][2] = p2; sacc[n][mt][3] = p3;
                lsum[mt][0] += p0 + p1;
                lsum[mt][1] += p2 + p3;
            }
        }

        if (jb < 3) {
            __half* Vn = nxt + KBUF;
            int c0 = tid, c1 = tid + 256;
#pragma unroll
            for (int pass = 0; pass < 2; pass++) {
                int c = pass ? c1 : c0;
                uint4 u = pass ? v1 : v0;
                int row = c / 9, k = c - row * 9;
                __half2 h0 = *reinterpret_cast<__half2*>(&u.x);
                __half2 h1 = *reinterpret_cast<__half2*>(&u.y);
                __half2 h2 = *reinterpret_cast<__half2*>(&u.z);
                __half2 h3 = *reinterpret_cast<__half2*>(&u.w);
                __half* d = Vn + 8 * k * VP + row;
                d[0 * VP] = h0.x; d[1 * VP] = h0.y;
                d[2 * VP] = h1.x; d[3 * VP] = h1.y;
                d[4 * VP] = h2.x; d[5 * VP] = h2.y;
                d[6 * VP] = h3.x; d[7 * VP] = h3.y;
            }
            if (tid < 64) {
                int c2 = tid + 512;
                int row = c2 / 9, k = c2 - row * 9;
                __half2 h0 = *reinterpret_cast<__half2*>(&v2.x);
                __half2 h1 = *reinterpret_cast<__half2*>(&v2.y);
                __half2 h2 = *reinterpret_cast<__half2*>(&v2.z);
                __half2 h3 = *reinterpret_cast<__half2*>(&v2.w);
                __half* d = Vn + 8 * k * VP + row;
                d[0 * VP] = h0.x; d[1 * VP] = h0.y;
                d[2 * VP] = h1.x; d[3 * VP] = h1.y;
                d[4 * VP] = h2.x; d[5 * VP] = h2.y;
                d[6 * VP] = h3.x; d[7 * VP] = h3.y;
            }
        }

        const __half* Vt = cur + KBUF;
#pragma unroll
        for (int kt2 = 0; kt2 < 4; kt2++) {
            uint32_t bfr[9][2];
#pragma unroll
            for (int vn = 0; vn < 4; vn++) {
                uint32_t bd = smem_u32(Vt + (16 * vn) * VP + 16 * kt2 + loffV);
                LDMX4(bfr[2 * vn][0], bfr[2 * vn + 1][0],
                      bfr[2 * vn][1], bfr[2 * vn + 1][1], bd);
            }
            {
                uint32_t bd = smem_u32(Vt + (64 + (lane & 7)) * VP + 16 * kt2 +
                                       ((lane >> 3) & 1) * 8);
                LDMX2(bfr[8][0], bfr[8][1], bd);
            }
#pragma unroll
            for (int mt = 0; mt < 2; mt++) {
                uint32_t afr[4];
                afr[0] = packh2(sacc[2 * kt2][mt][0], sacc[2 * kt2][mt][1]);
                afr[1] = packh2(sacc[2 * kt2][mt][2], sacc[2 * kt2][mt][3]);
                afr[2] = packh2(sacc[2 * kt2 + 1][mt][0], sacc[2 * kt2 + 1][mt][1]);
                afr[3] = packh2(sacc[2 * kt2 + 1][mt][2], sacc[2 * kt2 + 1][mt][3]);
#pragma unroll
                for (int n = 0; n < 9; n++) MMA_F16(oacc[mt][n], afr, bfr[n]);
            }
        }
        __syncthreads();
    }

#pragma unroll
    for (int mt = 0; mt < 2; mt++)
#pragma unroll
        for (int half = 0; half < 2; half++) {
            float l = lsum[mt][half];
            l += __shfl_xor_sync(0xffffffffu, l, 1);
            l += __shfl_xor_sync(0xffffffffu, l, 2);
            lsum[mt][half] = 1.f / l;
        }
#pragma unroll
    for (int mt = 0; mt < 2; mt++) {
        int row0 = seq * 256 + qb + 16 * mt + g;
        float i0 = lsum[mt][0], i1 = lsum[mt][1];
#pragma unroll
        for (int n = 0; n < 9; n++) {
            int col = h * HDx + 8 * n + 2 * tig;
            st2(o + (size_t)row0 * Dx + col, oacc[mt][n][0] * i0, oacc[mt][n][1] * i0);
            st2(o + (size_t)(row0 + 8) * Dx + col, oacc[mt][n][2] * i1, oacc[mt][n][3] * i1);
        }
    }
}

// temporal attention with fused QK-RMS, uint4-vectorized loads ---------------
__global__ void attn_t_kernel(const __half* __restrict__ qkv, __half* __restrict__ o,
                              const float* __restrict__ qn, const float* __restrict__ kn,
                              float scale) {
    int gid = blockIdx.x * 256 + threadIdx.x;
    int lane = threadIdx.x & 31;
    int qi = gid & 15;
    int pair = gid >> 4;
    int h = pair & 15;
    int seq = pair >> 4;
    const __half* qr = qkv + (size_t)(seq * 16 + qi) * D3 + h * HDx;
    float q[HDx];
    float ssq = 0.f;
#pragma unroll
    for (int t = 0; t < 9; t++) {
        uint4 u = *reinterpret_cast<const uint4*>(qr + 8 * t);
        const __half2* hp = reinterpret_cast<const __half2*>(&u);
#pragma unroll
        for (int i = 0; i < 4; i++) {
            float2 f = __half22float2(hp[i]);
            q[8 * t + 2 * i] = f.x;
            q[8 * t + 2 * i + 1] = f.y;
            ssq += f.x * f.x + f.y * f.y;
        }
    }
    float rq = rsqrtf(ssq * (1.f / HDx) + 1e-6f);
#pragma unroll
    for (int d = 0; d < HDx; d++) q[d] *= rq * __ldg(qn + d) * __ldg(kn + d);
    {
        const __half* kr = qkv + (size_t)(seq * 16 + qi) * D3 + Dx + h * HDx;
        float ssk = 0.f;
#pragma unroll
        for (int t = 0; t < 9; t++) {
            uint4 u = *reinterpret_cast<const uint4*>(kr + 8 * t);
            const __half2* hp = reinterpret_cast<const __half2*>(&u);
#pragma unroll
            for (int i = 0; i < 4; i++) {
                float2 f = __half22float2(hp[i]);
                ssk += f.x * f.x + f.y * f.y;
            }
        }
        ssq = rsqrtf(ssk * (1.f / HDx) + 1e-6f);
    }
    float s[16];
    float l = 0.f;
#pragma unroll
    for (int j = 0; j < 16; j++) {
        const __half* kr = qkv + (size_t)(seq * 16 + j) * D3 + Dx + h * HDx;
        float dot = 0.f;
#pragma unroll
        for (int t = 0; t < 9; t++) {
            uint4 u = *reinterpret_cast<const uint4*>(kr + 8 * t);
            const __half2* hp = reinterpret_cast<const __half2*>(&u);
#pragma unroll
            for (int i = 0; i < 4; i++) {
                float2 f = __half22float2(hp[i]);
                dot += q[8 * t + 2 * i] * f.x + q[8 * t + 2 * i + 1] * f.y;
            }
        }
        float rk = __shfl_sync(0xffffffffu, ssq, (lane & 16) | j);
        float p = __expf(dot * rk * scale);
        s[j] = p;
        l += p;
    }
    float inv = 1.f / l;
    __half* orow = o + (size_t)(seq * 16 + qi) * Dx + h * HDx;
    const __half* vbase = qkv + (size_t)(seq * 16) * D3 + 2 * Dx + h * HDx;
#pragma unroll
    for (int t = 0; t < 9; t++) {
        float acc[8] = {0.f, 0.f, 0.f, 0.f, 0.f, 0.f, 0.f, 0.f};
#pragma unroll
        for (int j = 0; j < 16; j++) {
            uint4 u = *reinterpret_cast<const uint4*>(vbase + (size_t)j * D3 + 8 * t);
            const __half2* hp = reinterpret_cast<const __half2*>(&u);
            float sj = s[j];
#pragma unroll
            for (int i = 0; i < 4; i++) {
                float2 f = __half22float2(hp[i]);
                acc[2 * i] += sj * f.x;
                acc[2 * i + 1] += sj * f.y;
            }
        }
        __half2* op = reinterpret_cast<__half2*>(orow + 8 * t);
#pragma unroll
        for (int i = 0; i < 4; i++)
            op[i] = __floats2half2_rn(acc[2 * i] * inv, acc[2 * i + 1] * inv);
    }
}

// ------------------------------- launch ------------------------------------
extern "C" void kernel_launch(void* const* d_in, const int* in_sizes, int n_in,
                              void* d_out, int out_size) {
    const float* x        = (const float*)d_in[0];
    const float* c        = (const float*)d_in[1];
    const float* norm1_w  = (const float*)d_in[2];
    const float* norm2_w  = (const float*)d_in[3];
    const float* norm3_w  = (const float*)d_in[4];
    const float* qn_s     = (const float*)d_in[5];
    const float* kn_s     = (const float*)d_in[6];
    const float* qkv_s_w  = (const float*)d_in[7];
    const float* qkv_s_b  = (const float*)d_in[8];
    const float* proj_s_w = (const float*)d_in[9];
    const float* proj_s_b = (const float*)d_in[10];
    const float* qn_t     = (const float*)d_in[11];
    const float* kn_t     = (const float*)d_in[12];
    const float* qkv_t_w  = (const float*)d_in[13];
    const float* qkv_t_b  = (const float*)d_in[14];
    const float* proj_t_w = (const float*)d_in[15];
    const float* proj_t_b = (const float*)d_in[16];
    const float* w12_w    = (const float*)d_in[17];
    const float* w12_b    = (const float*)d_in[18];
    const float* w3_w     = (const float*)d_in[19];
    const float* w3_b     = (const float*)d_in[20];
    const float* ada_w    = (const float*)d_in[21];
    const float* ada_b    = (const float*)d_in[22];
    float* out = (float*)d_out;

    float *p_ch;
    __half *p_xn, *p_bigh, *p_h;
    __half *pw_qkv_s, *pw_qkv_t, *pw_proj_s, *pw_proj_t, *pw_w12, *pw_w3;
    cudaGetSymbolAddress((void**)&p_ch, g_ch);
    cudaGetSymbolAddress((void**)&p_xn, g_xn);
    cudaGetSymbolAddress((void**)&p_bigh, g_bigh);
    cudaGetSymbolAddress((void**)&p_h, g_h);
    cudaGetSymbolAddress((void**)&pw_qkv_s, g_wt_qkv_s);
    cudaGetSymbolAddress((void**)&pw_qkv_t, g_wt_qkv_t);
    cudaGetSymbolAddress((void**)&pw_proj_s, g_wt_proj_s);
    cudaGetSymbolAddress((void**)&pw_proj_t, g_wt_proj_t);
    cudaGetSymbolAddress((void**)&pw_w12, g_wt_w12);
    cudaGetSymbolAddress((void**)&pw_w3, g_wt_w3);

    cudaFuncSetAttribute(gemm3_kernel<0, __half>,
                         cudaFuncAttributeMaxDynamicSharedMemorySize, GM3_SMEM);
    cudaFuncSetAttribute(gemm3_kernel<1, float>,
                         cudaFuncAttributeMaxDynamicSharedMemorySize, GM3_SMEM);
    cudaFuncSetAttribute(gemm3_kernel<2, __half>,
                         cudaFuncAttributeMaxDynamicSharedMemorySize, GM3_SMEM);
    cudaFuncSetAttribute(attn_s_mma_kernel, cudaFuncAttributeMaxDynamicSharedMemorySize,
                         AS_SMEM_H * 2);

    cudaStream_t s = 0;
    cudaStream_t s1 = g_ss.s;
    const float scale = 0.11785113019775793f;  // 1/sqrt(72)
    dim3 tb(32, 8);

    // ---- fork side stream for all weight transposes ----
    cudaEventRecord(g_ss.evRoot, s);
    cudaStreamWaitEvent(s1, g_ss.evRoot, 0);
    transpose_h_kernel<<<dim3(D3 / 32, Dx / 32), tb, 0, s1>>>(qkv_s_w, pw_qkv_s, Dx, D3);
    transpose_h_kernel<<<dim3(Dx / 32, Dx / 32), tb, 0, s1>>>(proj_s_w, pw_proj_s, Dx, Dx);
    cudaEventRecord(g_ss.evA, s1);
    transpose_h_kernel<<<dim3(D3 / 32, Dx / 32), tb, 0, s1>>>(qkv_t_w, pw_qkv_t, Dx, D3);
    transpose_h_kernel<<<dim3(Dx / 32, Dx / 32), tb, 0, s1>>>(proj_t_w, pw_proj_t, Dx, Dx);
    transpose_h_il_kernel<<<dim3(2 * MLPH / 32, Dx / 32), tb, 0, s1>>>(w12_w, pw_w12, Dx,
                                                                       2 * MLPH);
    transpose_h_kernel<<<dim3(Dx / 32, MLPH / 32), tb, 0, s1>>>(w3_w, pw_w3, MLPH, Dx);
    cudaEventRecord(g_ss.evB, s1);

    // ---- main chain on stream 0 ----
    {
        dim3 grid(D9 / TSZ, 1);
        dim3 blk(16, 16);
        gemm_bias_silu_kernel<<<grid, blk, 0, s>>>(c, ada_w, ada_b, p_ch, Bx, D9, Dx);
    }
    modrms_kernel<<<NTOK, 256, 0, s>>>(x, norm1_w, p_ch, 0, 1, p_xn, 0);

    // Stage 1: spatial attention
    cudaStreamWaitEvent(s, g_ss.evA, 0);
    gemm3_kernel<0, __half><<<dim3(D3 / BN3, NTOK / BM3), 256, GM3_SMEM, s>>>(
        p_xn, pw_qkv_s, qkv_s_b, p_bigh, NTOK, D3, Dx, nullptr, nullptr, 0, 0);
    attn_s_mma_kernel<<<32 * NHx, 256, AS_SMEM_H * 2, s>>>(p_bigh, p_xn, qn_s, kn_s);
    gemm3_kernel<1, float><<<dim3(Dx / BN3, NTOK / BM3), 256, GM3_SMEM, s>>>(
        p_xn, pw_proj_s, proj_s_b, out, NTOK, Dx, Dx, x, p_ch, 2, 0);

    // Stage 2: temporal attention
    modrms_kernel<<<NTOK, 256, 0, s>>>(out, norm2_w, p_ch, 3, 4, p_xn, 1);
    cudaStreamWaitEvent(s, g_ss.evB, 0);
    gemm3_kernel<0, __half><<<dim3(D3 / BN3, NTOK / BM3), 256, GM3_SMEM, s>>>(
        p_xn, pw_qkv_t, qkv_t_b, p_bigh, NTOK, D3, Dx, nullptr, nullptr, 0, 0);
    attn_t_kernel<<<512, 256, 0, s>>>(p_bigh, p_xn, qn_t, kn_t, scale);
    gemm3_kernel<1, float><<<dim3(Dx / BN3, NTOK / BM3), 256, GM3_SMEM, s>>>(
        p_xn, pw_proj_t, proj_t_b, out, NTOK, Dx, Dx, out, p_ch, 5, 1);

    // Stage 3: MLP
    modrms_kernel<<<NTOK, 256, 0, s>>>(out, norm3_w, p_ch, 6, 7, p_xn, 0);
    gemm3_kernel<2, __half><<<dim3(2 * MLPH / BN3, NTOK / BM3), 256, GM3_SMEM, s>>>(
        p_xn, pw_w12, w12_b, p_h, NTOK, 2 * MLPH, Dx, nullptr, nullptr, 0, 0);
    gemm3_kernel<1, float><<<dim3(Dx / BN3, NTOK / BM3), 256, GM3_SMEM, s>>>(
        p_h, pw_w3, w3_b, out, NTOK, Dx, MLPH, out, p_ch, 8, 0);
}